// round 1
// baseline (speedup 1.0000x reference)
#include <cuda_runtime.h>
#include <cstddef>

#define BATCH   2
#define SEQLEN  4096
#define DMODEL  512
#define DINNER  1024
#define NH      16
#define HD      64
#define DSTATE  64
#define CONVDIM 1152
#define DPROJ   2192
#define NPOS    (BATCH * SEQLEN)   // 8192
#define NC      64                 // chunks per sequence
#define CS      64                 // chunk size
#define EPSV    1e-5f

// ---------------- scratch (static device globals; no allocations) ----------
__device__ float g_zx [(size_t)NPOS * DPROJ];     // in-proj output
__device__ float g_xbc[(size_t)NPOS * CONVDIM];   // conv+silu output
__device__ float g_dt [NPOS * NH];                // softplus(dt)
__device__ float g_la [NPOS * NH];                // dt * A  (log decay per step)
__device__ float g_cl [BATCH * NH * SEQLEN];      // within-chunk inclusive cumsum of la
__device__ float g_S  [(size_t)BATCH * NH * NC * HD * DSTATE]; // chunk states -> prefix states
__device__ float g_y  [(size_t)NPOS * DINNER];    // SSM output (pre-gate)
__device__ float g_yn [(size_t)NPOS * DINNER];    // gated+normed

// ---------------- SGEMM: C[M,N] = A[M,K] @ B[K,N], fp32, 128x128x8 ----------
__global__ __launch_bounds__(256) void sgemm_kernel(
    const float* __restrict__ A, const float* __restrict__ B, float* __restrict__ C,
    int M, int N, int K) {
  __shared__ float As[8][128];
  __shared__ float Bs[8][128];
  const int tid  = threadIdx.x;
  const int bm   = blockIdx.y * 128;
  const int bn   = blockIdx.x * 128;
  const int arow = tid >> 1, acol = (tid & 1) << 2;
  const int brow = tid >> 5, bcol = (tid & 31) << 2;
  const int tr   = (tid >> 4) << 3;
  const int tc   = (tid & 15) << 3;
  float acc[8][8];
  #pragma unroll
  for (int i = 0; i < 8; i++)
    #pragma unroll
    for (int j = 0; j < 8; j++) acc[i][j] = 0.f;

  const float* Aptr = A + (size_t)(bm + arow) * K + acol;
  for (int k0 = 0; k0 < K; k0 += 8) {
    float4 av = *(const float4*)(Aptr + k0);
    As[acol + 0][arow] = av.x; As[acol + 1][arow] = av.y;
    As[acol + 2][arow] = av.z; As[acol + 3][arow] = av.w;
    const int col = bn + bcol;
    if (col < N) {
      *(float4*)&Bs[brow][bcol] = *(const float4*)(B + (size_t)(k0 + brow) * N + col);
    } else {
      Bs[brow][bcol] = 0.f; Bs[brow][bcol + 1] = 0.f;
      Bs[brow][bcol + 2] = 0.f; Bs[brow][bcol + 3] = 0.f;
    }
    __syncthreads();
    #pragma unroll
    for (int k = 0; k < 8; k++) {
      float4 a0 = *(float4*)&As[k][tr], a1 = *(float4*)&As[k][tr + 4];
      float4 b0 = *(float4*)&Bs[k][tc], b1 = *(float4*)&Bs[k][tc + 4];
      float a[8] = {a0.x, a0.y, a0.z, a0.w, a1.x, a1.y, a1.z, a1.w};
      float b[8] = {b0.x, b0.y, b0.z, b0.w, b1.x, b1.y, b1.z, b1.w};
      #pragma unroll
      for (int i = 0; i < 8; i++)
        #pragma unroll
        for (int j = 0; j < 8; j++) acc[i][j] += a[i] * b[j];
    }
    __syncthreads();
  }
  #pragma unroll
  for (int i = 0; i < 8; i++) {
    size_t ro = (size_t)(bm + tr + i) * N;
    #pragma unroll
    for (int jj = 0; jj < 8; jj += 4) {
      int col = bn + tc + jj;
      if (col < N)
        *(float4*)&C[ro + col] =
            make_float4(acc[i][jj], acc[i][jj + 1], acc[i][jj + 2], acc[i][jj + 3]);
    }
  }
}

// ---------------- depthwise causal conv (D_CONV=4) + bias + SiLU ------------
__global__ void conv_kernel(const float* __restrict__ cw, const float* __restrict__ cb) {
  size_t idx = (size_t)blockIdx.x * 256 + threadIdx.x;
  if (idx >= (size_t)NPOS * CONVDIM) return;
  int   ch  = (int)(idx % CONVDIM);
  size_t pos = idx / CONVDIM;
  int   l   = (int)(pos & (SEQLEN - 1));
  const float* src = g_zx + pos * DPROJ + DINNER + ch;
  float w0 = cw[ch * 4 + 0], w1 = cw[ch * 4 + 1], w2 = cw[ch * 4 + 2], w3 = cw[ch * 4 + 3];
  float acc = cb[ch] + w3 * src[0];
  if (l >= 1) acc += w2 * src[-(ptrdiff_t)DPROJ];
  if (l >= 2) acc += w1 * src[-2 * (ptrdiff_t)DPROJ];
  if (l >= 3) acc += w0 * src[-3 * (ptrdiff_t)DPROJ];
  g_xbc[idx] = acc / (1.f + __expf(-acc));   // silu
}

// ---------------- dt softplus + log-decay ----------------------------------
__global__ void dt_kernel(const float* __restrict__ dtb, const float* __restrict__ alog) {
  int idx = blockIdx.x * 256 + threadIdx.x;   // NPOS*NH = 131072 exactly
  int h = idx & (NH - 1);
  int pos = idx >> 4;
  float v  = g_zx[(size_t)pos * DPROJ + DINNER + CONVDIM + h] + dtb[h];
  float sp = (v > 20.f) ? v : log1pf(expf(v));
  g_dt[idx] = sp;
  g_la[idx] = -expf(alog[h]) * sp;            // la = dt * A, A = -exp(A_log)
}

// ---------------- per-chunk inclusive cumsum of la --------------------------
__global__ void cumlog_kernel() {
  int idx = blockIdx.x * 256 + threadIdx.x;   // B*NH*NC = 2048 exactly
  int c  = idx & (NC - 1);
  int bh = idx >> 6;
  int b  = bh >> 4, h = bh & (NH - 1);
  int t0 = c * CS;
  float cum = 0.f;
  for (int t = 0; t < CS; t++) {
    cum += g_la[((b * SEQLEN + t0 + t) << 4) + h];
    g_cl[bh * SEQLEN + t0 + t] = cum;
  }
}

// ---------------- intra-chunk SSD kernel ------------------------------------
// Per (b,h,c): Y_intra = M @ X (+ D*x) and chunk state S_c = (w⊙X)^T @ B
__global__ __launch_bounds__(256) void chunk_kernel(const float* __restrict__ Dv) {
  extern __shared__ float sm[];
  float* sB  = sm;              // [64][65]  B_t
  float* sCX = sm + 4160;       // [64][65]  C_t, later reused as XW = w_s * X_s
  float* sX  = sm + 8320;       // [64][65]  x_ssm
  float* sM  = sm + 12480;      // [64][65]  masked decay matrix
  float* scl = sm + 16640;      // [64]
  float* sdt = sm + 16704;      // [64]

  const int bid = blockIdx.x;
  const int c  = bid & (NC - 1);
  const int bh = bid >> 6;
  const int h  = bh & (NH - 1);
  const int b  = bh >> 4;
  const int tid = threadIdx.x;
  const int t0 = c * CS;

  for (int i = tid; i < 1024; i += 256) {
    int row = i >> 4, col = (i & 15) << 2;
    const float* base = g_xbc + (size_t)(b * SEQLEN + t0 + row) * CONVDIM;
    float4 vb = *(const float4*)(base + DINNER + col);
    float4 vc = *(const float4*)(base + DINNER + DSTATE + col);
    float4 vx = *(const float4*)(base + h * HD + col);
    int o = row * 65 + col;
    sB [o] = vb.x; sB [o + 1] = vb.y; sB [o + 2] = vb.z; sB [o + 3] = vb.w;
    sCX[o] = vc.x; sCX[o + 1] = vc.y; sCX[o + 2] = vc.z; sCX[o + 3] = vc.w;
    sX [o] = vx.x; sX [o + 1] = vx.y; sX [o + 2] = vx.z; sX [o + 3] = vx.w;
  }
  if (tid < 64) {
    scl[tid] = g_cl[bh * SEQLEN + t0 + tid];
    sdt[tid] = g_dt[(b * SEQLEN + t0 + tid) * NH + h];
  }
  __syncthreads();

  const int tr = (tid >> 4) << 2;   // t-tile
  const int sc = (tid & 15) << 2;   // s-tile (also p / n tile later)

  // M0[t][s] = C_t . B_s
  float mm[4][4];
  #pragma unroll
  for (int i = 0; i < 4; i++)
    #pragma unroll
    for (int j = 0; j < 4; j++) mm[i][j] = 0.f;
  for (int n = 0; n < 64; ++n) {
    float cf[4], bf[4];
    #pragma unroll
    for (int i = 0; i < 4; i++) cf[i] = sCX[(tr + i) * 65 + n];
    #pragma unroll
    for (int j = 0; j < 4; j++) bf[j] = sB[(sc + j) * 65 + n];
    #pragma unroll
    for (int i = 0; i < 4; i++)
      #pragma unroll
      for (int j = 0; j < 4; j++) mm[i][j] += cf[i] * bf[j];
  }
  const float Ltot = scl[63];
  #pragma unroll
  for (int i = 0; i < 4; i++)
    #pragma unroll
    for (int j = 0; j < 4; j++) {
      int t = tr + i, s = sc + j;
      mm[i][j] = (s <= t) ? mm[i][j] * __expf(scl[t] - scl[s]) * sdt[s] : 0.f;
    }
  __syncthreads();   // all reads of sCX (C) done before overwrite

  #pragma unroll
  for (int i = 0; i < 4; i++)
    #pragma unroll
    for (int j = 0; j < 4; j++) sM[(tr + i) * 65 + sc + j] = mm[i][j];
  for (int i = tid; i < 1024; i += 256) {
    int row = i >> 4, col = (i & 15) << 2;
    float w = __expf(Ltot - scl[row]) * sdt[row];
    int o = row * 65 + col;
    sCX[o]     = w * sX[o];
    sCX[o + 1] = w * sX[o + 1];
    sCX[o + 2] = w * sX[o + 2];
    sCX[o + 3] = w * sX[o + 3];
  }
  __syncthreads();

  // Y[t][p] = sum_s M[t][s] X[s][p]   ;   S[p][n] = sum_s XW[s][p] B[s][n]
  float yy[4][4], ss[4][4];
  #pragma unroll
  for (int i = 0; i < 4; i++)
    #pragma unroll
    for (int j = 0; j < 4; j++) { yy[i][j] = 0.f; ss[i][j] = 0.f; }
  for (int k = 0; k < 64; ++k) {
    float mv[4], xw[4], xv[4], bn[4];
    #pragma unroll
    for (int i = 0; i < 4; i++) {
      mv[i] = sM[(tr + i) * 65 + k];
      xw[i] = sCX[k * 65 + tr + i];
    }
    #pragma unroll
    for (int j = 0; j < 4; j++) {
      xv[j] = sX[k * 65 + sc + j];
      bn[j] = sB[k * 65 + sc + j];
    }
    #pragma unroll
    for (int i = 0; i < 4; i++)
      #pragma unroll
      for (int j = 0; j < 4; j++) {
        yy[i][j] += mv[i] * xv[j];
        ss[i][j] += xw[i] * bn[j];
      }
  }

  const float Dh = Dv[h];
  #pragma unroll
  for (int i = 0; i < 4; i++) {
    float4 o4;
    o4.x = yy[i][0] + Dh * sX[(tr + i) * 65 + sc + 0];
    o4.y = yy[i][1] + Dh * sX[(tr + i) * 65 + sc + 1];
    o4.z = yy[i][2] + Dh * sX[(tr + i) * 65 + sc + 2];
    o4.w = yy[i][3] + Dh * sX[(tr + i) * 65 + sc + 3];
    *(float4*)(g_y + (size_t)(b * SEQLEN + t0 + tr + i) * DINNER + h * HD + sc) = o4;
    float4 s4 = make_float4(ss[i][0], ss[i][1], ss[i][2], ss[i][3]);
    *(float4*)(g_S + (size_t)bid * 4096 + (tr + i) * 64 + sc) = s4;
  }
}

// ---------------- inter-chunk state scan (in-place exclusive prefix) --------
__global__ __launch_bounds__(256) void scan_kernel() {
  const int bh = blockIdx.x, tid = threadIdx.x;
  float run[16];
  #pragma unroll
  for (int i = 0; i < 16; i++) run[i] = 0.f;
  for (int c = 0; c < NC; c++) {
    float a = __expf(g_cl[bh * SEQLEN + c * CS + CS - 1]);
    float* base = g_S + (size_t)(bh * NC + c) * 4096;
    #pragma unroll
    for (int g = 0; g < 4; g++) {
      float* p = base + ((size_t)g * 256 + tid) * 4;
      float4 v = *(float4*)p;
      *(float4*)p = make_float4(run[4 * g], run[4 * g + 1], run[4 * g + 2], run[4 * g + 3]);
      run[4 * g]     = a * run[4 * g]     + v.x;
      run[4 * g + 1] = a * run[4 * g + 1] + v.y;
      run[4 * g + 2] = a * run[4 * g + 2] + v.z;
      run[4 * g + 3] = a * run[4 * g + 3] + v.w;
    }
  }
}

// ---------------- inter-chunk contribution: Y += exp(cum[t]) * C @ Sprev^T --
__global__ __launch_bounds__(256) void inter_kernel() {
  __shared__ float sS[4160];   // [p][n] prefix state
  __shared__ float sC[4160];   // [t][n]
  __shared__ float scl[64];
  const int bid = blockIdx.x;
  const int c  = bid & (NC - 1);
  const int bh = bid >> 6;
  const int h  = bh & (NH - 1);
  const int b  = bh >> 4;
  const int tid = threadIdx.x;
  const int t0 = c * CS;

  for (int i = tid; i < 1024; i += 256) {
    int row = i >> 4, col = (i & 15) << 2;
    float4 v = *(const float4*)(g_S + (size_t)bid * 4096 + row * 64 + col);
    int o = row * 65 + col;
    sS[o] = v.x; sS[o + 1] = v.y; sS[o + 2] = v.z; sS[o + 3] = v.w;
    float4 vc = *(const float4*)(g_xbc + (size_t)(b * SEQLEN + t0 + row) * CONVDIM
                                 + DINNER + DSTATE + col);
    sC[o] = vc.x; sC[o + 1] = vc.y; sC[o + 2] = vc.z; sC[o + 3] = vc.w;
  }
  if (tid < 64) scl[tid] = g_cl[bh * SEQLEN + t0 + tid];
  __syncthreads();

  const int tr = (tid >> 4) << 2;   // t
  const int pc = (tid & 15) << 2;   // p
  float acc[4][4];
  #pragma unroll
  for (int i = 0; i < 4; i++)
    #pragma unroll
    for (int j = 0; j < 4; j++) acc[i][j] = 0.f;
  for (int n = 0; n < 64; ++n) {
    float cf[4], sf[4];
    #pragma unroll
    for (int i = 0; i < 4; i++) cf[i] = sC[(tr + i) * 65 + n];
    #pragma unroll
    for (int j = 0; j < 4; j++) sf[j] = sS[(pc + j) * 65 + n];
    #pragma unroll
    for (int i = 0; i < 4; i++)
      #pragma unroll
      for (int j = 0; j < 4; j++) acc[i][j] += cf[i] * sf[j];
  }
  #pragma unroll
  for (int i = 0; i < 4; i++) {
    float e = __expf(scl[tr + i]);
    size_t o = (size_t)(b * SEQLEN + t0 + tr + i) * DINNER + h * HD + pc;
    float4 cur = *(float4*)(g_y + o);
    cur.x += e * acc[i][0]; cur.y += e * acc[i][1];
    cur.z += e * acc[i][2]; cur.w += e * acc[i][3];
    *(float4*)(g_y + o) = cur;
  }
}

// ---------------- gate (y * silu(z)) + RMSNorm -------------------------------
__global__ __launch_bounds__(256) void norm_kernel(const float* __restrict__ nw) {
  const int pos = blockIdx.x, tid = threadIdx.x;
  float4 yv = *(const float4*)(g_y  + (size_t)pos * DINNER + tid * 4);
  float4 zv = *(const float4*)(g_zx + (size_t)pos * DPROJ  + tid * 4);
  float4 g;
  g.x = yv.x * (zv.x / (1.f + __expf(-zv.x)));
  g.y = yv.y * (zv.y / (1.f + __expf(-zv.y)));
  g.z = yv.z * (zv.z / (1.f + __expf(-zv.z)));
  g.w = yv.w * (zv.w / (1.f + __expf(-zv.w)));
  float ssq = g.x * g.x + g.y * g.y + g.z * g.z + g.w * g.w;
  #pragma unroll
  for (int o = 16; o; o >>= 1) ssq += __shfl_xor_sync(0xFFFFFFFFu, ssq, o);
  __shared__ float red[8];
  if ((tid & 31) == 0) red[tid >> 5] = ssq;
  __syncthreads();
  float tot = red[0] + red[1] + red[2] + red[3] + red[4] + red[5] + red[6] + red[7];
  float scale = rsqrtf(tot * (1.f / DINNER) + EPSV);
  float4 w = *(const float4*)(nw + tid * 4);
  float4 o4 = make_float4(g.x * scale * w.x, g.y * scale * w.y,
                          g.z * scale * w.z, g.w * scale * w.w);
  *(float4*)(g_yn + (size_t)pos * DINNER + tid * 4) = o4;
}

// ---------------- launch ------------------------------------------------------
extern "C" void kernel_launch(void* const* d_in, const int* in_sizes, int n_in,
                              void* d_out, int out_size) {
  const float* x       = (const float*)d_in[0];
  const float* W_in    = (const float*)d_in[1];
  const float* conv_w  = (const float*)d_in[2];
  const float* conv_b  = (const float*)d_in[3];
  const float* dt_bias = (const float*)d_in[4];
  const float* A_log   = (const float*)d_in[5];
  const float* Dv      = (const float*)d_in[6];
  const float* nw      = (const float*)d_in[7];
  const float* W_out   = (const float*)d_in[8];
  float* out = (float*)d_out;

  void* p;
  cudaGetSymbolAddress(&p, g_zx);  float* zx = (float*)p;
  cudaGetSymbolAddress(&p, g_yn);  float* yn = (float*)p;

  cudaFuncSetAttribute(chunk_kernel, cudaFuncAttributeMaxDynamicSharedMemorySize, 67072);

  dim3 blk(256);
  // 1) in-projection: zx = x @ W_in   (8192 x 2192 x 512)
  sgemm_kernel<<<dim3((DPROJ + 127) / 128, NPOS / 128), blk>>>(x, W_in, zx, NPOS, DPROJ, DMODEL);
  // 2) depthwise conv + silu
  conv_kernel<<<(unsigned)(((size_t)NPOS * CONVDIM + 255) / 256), blk>>>(conv_w, conv_b);
  // 3) dt softplus, log decay
  dt_kernel<<<(NPOS * NH) / 256, blk>>>(dt_bias, A_log);
  // 4) per-chunk cumlog
  cumlog_kernel<<<(BATCH * NH * NC) / 256, blk>>>();
  // 5) intra-chunk SSD
  chunk_kernel<<<BATCH * NH * NC, blk, 67072>>>(Dv);
  // 6) inter-chunk state scan
  scan_kernel<<<BATCH * NH, blk>>>();
  // 7) inter-chunk correction
  inter_kernel<<<BATCH * NH * NC, blk>>>();
  // 8) gate + RMSNorm
  norm_kernel<<<NPOS, blk>>>(nw);
  // 9) out-projection: out = yn @ W_out  (8192 x 512 x 1024)
  sgemm_kernel<<<dim3(DMODEL / 128, NPOS / 128), blk>>>(yn, W_out, out, NPOS, DMODEL, DINNER);
}

// round 3
// speedup vs baseline: 2.0832x; 2.0832x over previous
#include <cuda_runtime.h>
#include <cuda_bf16.h>
#include <cstdint>
#include <cstddef>

#define BATCH   2
#define SEQLEN  4096
#define DMODEL  512
#define DINNER  1024
#define NH      16
#define HD      64
#define DSTATE  64
#define CONVDIM 1152
#define DPROJ   2192
#define NPOS    (BATCH * SEQLEN)   // 8192
#define NC      64
#define CS      64
#define EPSV    1e-5f
#define NPAD1   2304               // 18*128 padded N for GEMM1

// ---------------- scratch (static device globals) ---------------------------
__device__ float g_zx [(size_t)NPOS * DPROJ];
__device__ float g_xbc[(size_t)NPOS * CONVDIM];
__device__ float g_dt [NPOS * NH];
__device__ float g_la [NPOS * NH];
__device__ float g_cl [BATCH * NH * SEQLEN];
__device__ float g_S  [(size_t)BATCH * NH * NC * HD * DSTATE];
__device__ float g_y  [(size_t)NPOS * DINNER];

// bf16 split operands for tensor-core GEMMs
__device__ __nv_bfloat16 g_xh [(size_t)NPOS * DMODEL];
__device__ __nv_bfloat16 g_xl [(size_t)NPOS * DMODEL];
__device__ __nv_bfloat16 g_w1h[(size_t)NPAD1 * DMODEL];
__device__ __nv_bfloat16 g_w1l[(size_t)NPAD1 * DMODEL];
__device__ __nv_bfloat16 g_yh [(size_t)NPOS * DINNER];
__device__ __nv_bfloat16 g_yl [(size_t)NPOS * DINNER];
__device__ __nv_bfloat16 g_w2h[(size_t)DMODEL * DINNER];
__device__ __nv_bfloat16 g_w2l[(size_t)DMODEL * DINNER];

// ---------------- PTX helpers (portable sm_80+ subset only) -----------------
__device__ __forceinline__ uint32_t smem_u32(const void* p) {
  uint32_t a;
  asm("{ .reg .u64 t; cvta.to.shared.u64 t, %1; cvt.u32.u64 %0, t; }" : "=r"(a) : "l"(p));
  return a;
}
__device__ __forceinline__ void ldm4(uint32_t* r, uint32_t addr) {
  asm volatile("ldmatrix.sync.aligned.m8n8.x4.shared.b16 {%0,%1,%2,%3}, [%4];"
               : "=r"(r[0]), "=r"(r[1]), "=r"(r[2]), "=r"(r[3]) : "r"(addr));
}
__device__ __forceinline__ void mma16816(float* c, const uint32_t* a, const uint32_t* b) {
  asm volatile(
      "mma.sync.aligned.m16n8k16.row.col.f32.bf16.bf16.f32 "
      "{%0,%1,%2,%3}, {%4,%5,%6,%7}, {%8,%9}, {%0,%1,%2,%3};"
      : "+f"(c[0]), "+f"(c[1]), "+f"(c[2]), "+f"(c[3])
      : "r"(a[0]), "r"(a[1]), "r"(a[2]), "r"(a[3]), "r"(b[0]), "r"(b[1]));
}
#define CPASYNC(dst, src) \
  asm volatile("cp.async.cg.shared.global [%0], [%1], 16;" :: "r"(dst), "l"(src))
#define CPCOMMIT() asm volatile("cp.async.commit_group;" ::: "memory")
#define CPWAIT(n)  asm volatile("cp.async.wait_group %0;" :: "n"(n) : "memory")
#define SWZ(off)   ((off) ^ (((off) >> 3) & 0x70))

// ---------------- HMMA GEMM: C[M,ldc] = (Ah+Al) @ (Bh+Bl)^T -----------------
// A[M][K] K-major bf16 split; B[Npad][K] K-major bf16 split; C fp32.
// CTA tile 128x128, K-chunk 64, cp.async double buffer, 8 warps (64x32 each).
#define SM_BUF   65536           // 4 tiles x 128 rows x 128B
#define SM_TOTAL (2 * SM_BUF)

__global__ __launch_bounds__(256) void gemm_tc(
    const __nv_bfloat16* __restrict__ Ah, const __nv_bfloat16* __restrict__ Al,
    const __nv_bfloat16* __restrict__ Bh, const __nv_bfloat16* __restrict__ Bl,
    float* __restrict__ C, int K, int N, int ldc) {
  extern __shared__ char smem[];
  const uint32_t sb = smem_u32(smem);
  const int tid = threadIdx.x, wid = tid >> 5, lane = tid & 31;
  const int bm = blockIdx.y * 128, bn = blockIdx.x * 128;
  const int wrow = wid & 1, wcol = wid >> 1;          // warp tile: 64(M) x 32(N)

  float acc[4][4][4];
  #pragma unroll
  for (int i = 0; i < 4; i++)
    #pragma unroll
    for (int j = 0; j < 4; j++)
      #pragma unroll
      for (int v = 0; v < 4; v++) acc[i][j][v] = 0.f;

  const int nK = K >> 6;

  // per-thread load indexing (16 x 16B per thread per chunk)
  // u = it*256 + tid ; tile = u>>10 (Ah,Al,Bh,Bl); idx = u & 1023; row=idx>>3, c16=idx&7
  // prologue: chunk 0 -> buf 0
  {
    const int k0 = 0;
    #pragma unroll
    for (int it = 0; it < 16; it++) {
      const int u = it * 256 + tid;
      const int tile = u >> 10, idx = u & 1023;
      const int row = idx >> 3, c16 = idx & 7;
      const uint32_t dst = sb + tile * 16384 + SWZ((uint32_t)(row * 128 + c16 * 16));
      const __nv_bfloat16* src =
          (tile == 0) ? Ah + (size_t)(bm + row) * K + k0 + c16 * 8 :
          (tile == 1) ? Al + (size_t)(bm + row) * K + k0 + c16 * 8 :
          (tile == 2) ? Bh + (size_t)(bn + row) * K + k0 + c16 * 8 :
                        Bl + (size_t)(bn + row) * K + k0 + c16 * 8;
      CPASYNC(dst, src);
    }
    CPCOMMIT();
  }

  for (int i = 0; i < nK; i++) {
    if (i + 1 < nK) {
      const int k0 = (i + 1) << 6;
      const uint32_t bbuf = sb + ((i + 1) & 1) * SM_BUF;
      #pragma unroll
      for (int it = 0; it < 16; it++) {
        const int u = it * 256 + tid;
        const int tile = u >> 10, idx = u & 1023;
        const int row = idx >> 3, c16 = idx & 7;
        const uint32_t dst = bbuf + tile * 16384 + SWZ((uint32_t)(row * 128 + c16 * 16));
        const __nv_bfloat16* src =
            (tile == 0) ? Ah + (size_t)(bm + row) * K + k0 + c16 * 8 :
            (tile == 1) ? Al + (size_t)(bm + row) * K + k0 + c16 * 8 :
            (tile == 2) ? Bh + (size_t)(bn + row) * K + k0 + c16 * 8 :
                          Bl + (size_t)(bn + row) * K + k0 + c16 * 8;
        CPASYNC(dst, src);
      }
      CPCOMMIT();
      CPWAIT(1);
    } else {
      CPWAIT(0);
    }
    __syncthreads();

    const uint32_t tb = sb + (i & 1) * SM_BUF;
    const int arow = wrow * 64 + (lane & 15);          // within-tile A row
    const int brow = wcol * 32 + (lane & 7) + ((lane >> 4) & 1) * 8;
    const int akb  = (lane >> 4) * 16;                 // A k-byte sub-offset
    const int bkb  = ((lane >> 3) & 1) * 16;           // B k-byte sub-offset

    #pragma unroll
    for (int ks = 0; ks < 4; ks++) {
      uint32_t ah[4][4], al[4][4], bh[2][4], bl[2][4];
      #pragma unroll
      for (int mt = 0; mt < 4; mt++) {
        const uint32_t off = SWZ((uint32_t)((arow + mt * 16) * 128 + ks * 32 + akb));
        ldm4(ah[mt], tb + off);
        ldm4(al[mt], tb + 16384 + off);
      }
      #pragma unroll
      for (int p = 0; p < 2; p++) {
        const uint32_t off = SWZ((uint32_t)((brow + p * 16) * 128 + ks * 32 + bkb));
        ldm4(bh[p], tb + 32768 + off);
        ldm4(bl[p], tb + 49152 + off);
      }
      #pragma unroll
      for (int mt = 0; mt < 4; mt++)
        #pragma unroll
        for (int p = 0; p < 2; p++) {
          // n-tiles 2p and 2p+1 ; b frag pairs (r0,r1) and (r2,r3)
          mma16816(acc[mt][2 * p],     ah[mt], &bh[p][0]);
          mma16816(acc[mt][2 * p + 1], ah[mt], &bh[p][2]);
          mma16816(acc[mt][2 * p],     ah[mt], &bl[p][0]);
          mma16816(acc[mt][2 * p + 1], ah[mt], &bl[p][2]);
          mma16816(acc[mt][2 * p],     al[mt], &bh[p][0]);
          mma16816(acc[mt][2 * p + 1], al[mt], &bh[p][2]);
        }
    }
    __syncthreads();
  }

  // epilogue: fp32 stores, predicated on col < N
  const int r0 = bm + wrow * 64 + (lane >> 2);
  const int c0 = bn + wcol * 32 + (lane & 3) * 2;
  #pragma unroll
  for (int mt = 0; mt < 4; mt++)
    #pragma unroll
    for (int nt = 0; nt < 4; nt++) {
      const int col = c0 + nt * 8;
      if (col < N) {
        const int row = r0 + mt * 16;
        *(float2*)&C[(size_t)row * ldc + col] =
            make_float2(acc[mt][nt][0], acc[mt][nt][1]);
        *(float2*)&C[(size_t)(row + 8) * ldc + col] =
            make_float2(acc[mt][nt][2], acc[mt][nt][3]);
      }
    }
}

// ---------------- split fp32 -> bf16 hi/lo ----------------------------------
__global__ void split_kernel(const float* __restrict__ src,
                             __nv_bfloat16* __restrict__ hi,
                             __nv_bfloat16* __restrict__ lo, int n) {
  int i = blockIdx.x * 256 + threadIdx.x;
  if (i >= n) return;
  float v = src[i];
  __nv_bfloat16 h = __float2bfloat16(v);
  hi[i] = h;
  lo[i] = __float2bfloat16(v - __bfloat162float(h));
}

// ---------------- W transpose + split: out[n][k] = W[k][n] ------------------
__global__ void wtrans_kernel(const float* __restrict__ W,
                              __nv_bfloat16* __restrict__ th,
                              __nv_bfloat16* __restrict__ tl, int K, int N) {
  __shared__ float t[32][33];
  const int n0 = blockIdx.x * 32, k0 = blockIdx.y * 32;
  const int tx = threadIdx.x, ty = threadIdx.y;
  #pragma unroll
  for (int r = 0; r < 4; r++) {
    int k = k0 + ty + r * 8, n = n0 + tx;
    t[ty + r * 8][tx] = (n < N) ? W[(size_t)k * N + n] : 0.f;
  }
  __syncthreads();
  #pragma unroll
  for (int r = 0; r < 4; r++) {
    int n = n0 + ty + r * 8, k = k0 + tx;
    float v = t[tx][ty + r * 8];
    __nv_bfloat16 h = __float2bfloat16(v);
    th[(size_t)n * K + k] = h;
    tl[(size_t)n * K + k] = __float2bfloat16(v - __bfloat162float(h));
  }
}

// ---------------- depthwise causal conv (D_CONV=4) + bias + SiLU ------------
__global__ void conv_kernel(const float* __restrict__ cw, const float* __restrict__ cb) {
  size_t idx = (size_t)blockIdx.x * 256 + threadIdx.x;
  if (idx >= (size_t)NPOS * CONVDIM) return;
  int ch = (int)(idx % CONVDIM);
  size_t pos = idx / CONVDIM;
  int l = (int)(pos & (SEQLEN - 1));
  const float* src = g_zx + pos * DPROJ + DINNER + ch;
  float w0 = cw[ch * 4 + 0], w1 = cw[ch * 4 + 1], w2 = cw[ch * 4 + 2], w3 = cw[ch * 4 + 3];
  float acc = cb[ch] + w3 * src[0];
  if (l >= 1) acc += w2 * src[-(ptrdiff_t)DPROJ];
  if (l >= 2) acc += w1 * src[-2 * (ptrdiff_t)DPROJ];
  if (l >= 3) acc += w0 * src[-3 * (ptrdiff_t)DPROJ];
  g_xbc[idx] = acc / (1.f + __expf(-acc));
}

// ---------------- dt softplus + log-decay -----------------------------------
__global__ void dt_kernel(const float* __restrict__ dtb, const float* __restrict__ alog) {
  int idx = blockIdx.x * 256 + threadIdx.x;
  int h = idx & (NH - 1);
  int pos = idx >> 4;
  float v = g_zx[(size_t)pos * DPROJ + DINNER + CONVDIM + h] + dtb[h];
  float sp = (v > 20.f) ? v : log1pf(expf(v));
  g_dt[idx] = sp;
  g_la[idx] = -expf(alog[h]) * sp;
}

// ---------------- per-chunk inclusive cumsum (one warp per chunk) -----------
__global__ void cumlog_kernel() {
  const int gw = (blockIdx.x * 256 + threadIdx.x) >> 5;   // 0..2047
  const int lane = threadIdx.x & 31;
  const int c = gw & (NC - 1);
  const int bh = gw >> 6;
  const int b = bh >> 4, h = bh & (NH - 1);
  const int t0 = c * CS;
  float x0 = g_la[((b * SEQLEN + t0 + lane) << 4) + h];
  float x1 = g_la[((b * SEQLEN + t0 + 32 + lane) << 4) + h];
  #pragma unroll
  for (int o = 1; o < 32; o <<= 1) {
    float v = __shfl_up_sync(0xFFFFFFFFu, x0, o);
    if (lane >= o) x0 += v;
  }
  float tot0 = __shfl_sync(0xFFFFFFFFu, x0, 31);
  #pragma unroll
  for (int o = 1; o < 32; o <<= 1) {
    float v = __shfl_up_sync(0xFFFFFFFFu, x1, o);
    if (lane >= o) x1 += v;
  }
  x1 += tot0;
  g_cl[bh * SEQLEN + t0 + lane] = x0;
  g_cl[bh * SEQLEN + t0 + 32 + lane] = x1;
}

// ---------------- intra-chunk SSD kernel -------------------------------------
__global__ __launch_bounds__(256) void chunk_kernel(const float* __restrict__ Dv) {
  extern __shared__ float sm[];
  float* sB  = sm;
  float* sCX = sm + 4160;
  float* sX  = sm + 8320;
  float* sM  = sm + 12480;
  float* scl = sm + 16640;
  float* sdt = sm + 16704;

  const int bid = blockIdx.x;
  const int c = bid & (NC - 1);
  const int bh = bid >> 6;
  const int h = bh & (NH - 1);
  const int b = bh >> 4;
  const int tid = threadIdx.x;
  const int t0 = c * CS;

  for (int i = tid; i < 1024; i += 256) {
    int row = i >> 4, col = (i & 15) << 2;
    const float* base = g_xbc + (size_t)(b * SEQLEN + t0 + row) * CONVDIM;
    float4 vb = *(const float4*)(base + DINNER + col);
    float4 vc = *(const float4*)(base + DINNER + DSTATE + col);
    float4 vx = *(const float4*)(base + h * HD + col);
    int o = row * 65 + col;
    sB [o] = vb.x; sB [o + 1] = vb.y; sB [o + 2] = vb.z; sB [o + 3] = vb.w;
    sCX[o] = vc.x; sCX[o + 1] = vc.y; sCX[o + 2] = vc.z; sCX[o + 3] = vc.w;
    sX [o] = vx.x; sX [o + 1] = vx.y; sX [o + 2] = vx.z; sX [o + 3] = vx.w;
  }
  if (tid < 64) {
    scl[tid] = g_cl[bh * SEQLEN + t0 + tid];
    sdt[tid] = g_dt[(b * SEQLEN + t0 + tid) * NH + h];
  }
  __syncthreads();

  const int tr = (tid >> 4) << 2;
  const int sc = (tid & 15) << 2;

  float mm[4][4];
  #pragma unroll
  for (int i = 0; i < 4; i++)
    #pragma unroll
    for (int j = 0; j < 4; j++) mm[i][j] = 0.f;
  for (int n = 0; n < 64; ++n) {
    float cf[4], bf[4];
    #pragma unroll
    for (int i = 0; i < 4; i++) cf[i] = sCX[(tr + i) * 65 + n];
    #pragma unroll
    for (int j = 0; j < 4; j++) bf[j] = sB[(sc + j) * 65 + n];
    #pragma unroll
    for (int i = 0; i < 4; i++)
      #pragma unroll
      for (int j = 0; j < 4; j++) mm[i][j] += cf[i] * bf[j];
  }
  const float Ltot = scl[63];
  #pragma unroll
  for (int i = 0; i < 4; i++)
    #pragma unroll
    for (int j = 0; j < 4; j++) {
      int t = tr + i, s = sc + j;
      mm[i][j] = (s <= t) ? mm[i][j] * __expf(scl[t] - scl[s]) * sdt[s] : 0.f;
    }
  __syncthreads();

  #pragma unroll
  for (int i = 0; i < 4; i++)
    #pragma unroll
    for (int j = 0; j < 4; j++) sM[(tr + i) * 65 + sc + j] = mm[i][j];
  for (int i = tid; i < 1024; i += 256) {
    int row = i >> 4, col = (i & 15) << 2;
    float w = __expf(Ltot - scl[row]) * sdt[row];
    int o = row * 65 + col;
    sCX[o]     = w * sX[o];
    sCX[o + 1] = w * sX[o + 1];
    sCX[o + 2] = w * sX[o + 2];
    sCX[o + 3] = w * sX[o + 3];
  }
  __syncthreads();

  float yy[4][4], ss[4][4];
  #pragma unroll
  for (int i = 0; i < 4; i++)
    #pragma unroll
    for (int j = 0; j < 4; j++) { yy[i][j] = 0.f; ss[i][j] = 0.f; }
  for (int k = 0; k < 64; ++k) {
    float mv[4], xw[4], xv[4], bn[4];
    #pragma unroll
    for (int i = 0; i < 4; i++) {
      mv[i] = sM[(tr + i) * 65 + k];
      xw[i] = sCX[k * 65 + tr + i];
    }
    #pragma unroll
    for (int j = 0; j < 4; j++) {
      xv[j] = sX[k * 65 + sc + j];
      bn[j] = sB[k * 65 + sc + j];
    }
    #pragma unroll
    for (int i = 0; i < 4; i++)
      #pragma unroll
      for (int j = 0; j < 4; j++) {
        yy[i][j] += mv[i] * xv[j];
        ss[i][j] += xw[i] * bn[j];
      }
  }

  const float Dh = Dv[h];
  #pragma unroll
  for (int i = 0; i < 4; i++) {
    float4 o4;
    o4.x = yy[i][0] + Dh * sX[(tr + i) * 65 + sc + 0];
    o4.y = yy[i][1] + Dh * sX[(tr + i) * 65 + sc + 1];
    o4.z = yy[i][2] + Dh * sX[(tr + i) * 65 + sc + 2];
    o4.w = yy[i][3] + Dh * sX[(tr + i) * 65 + sc + 3];
    *(float4*)(g_y + (size_t)(b * SEQLEN + t0 + tr + i) * DINNER + h * HD + sc) = o4;
    float4 s4 = make_float4(ss[i][0], ss[i][1], ss[i][2], ss[i][3]);
    *(float4*)(g_S + (size_t)bid * 4096 + (tr + i) * 64 + sc) = s4;
  }
}

// ---------------- inter-chunk state scan (widened: 32 x 8 blocks) -----------
__global__ __launch_bounds__(128) void scan_kernel() {
  const int bh = blockIdx.x;
  const int slice = blockIdx.y;              // 0..7, each covers 512 floats
  const int tid = threadIdx.x;
  const int off = slice * 512 + tid * 4;
  float run[4] = {0.f, 0.f, 0.f, 0.f};
  for (int c = 0; c < NC; c++) {
    float a = __expf(g_cl[bh * SEQLEN + c * CS + CS - 1]);
    float* p = g_S + (size_t)(bh * NC + c) * 4096 + off;
    float4 v = *(float4*)p;
    *(float4*)p = make_float4(run[0], run[1], run[2], run[3]);
    run[0] = a * run[0] + v.x;
    run[1] = a * run[1] + v.y;
    run[2] = a * run[2] + v.z;
    run[3] = a * run[3] + v.w;
  }
}

// ---------------- inter-chunk contribution -----------------------------------
__global__ __launch_bounds__(256) void inter_kernel() {
  __shared__ float sS[4160];
  __shared__ float sC[4160];
  __shared__ float scl[64];
  const int bid = blockIdx.x;
  const int c = bid & (NC - 1);
  const int bh = bid >> 6;
  const int h = bh & (NH - 1);
  const int b = bh >> 4;
  const int tid = threadIdx.x;
  const int t0 = c * CS;

  for (int i = tid; i < 1024; i += 256) {
    int row = i >> 4, col = (i & 15) << 2;
    float4 v = *(const float4*)(g_S + (size_t)bid * 4096 + row * 64 + col);
    int o = row * 65 + col;
    sS[o] = v.x; sS[o + 1] = v.y; sS[o + 2] = v.z; sS[o + 3] = v.w;
    float4 vc = *(const float4*)(g_xbc + (size_t)(b * SEQLEN + t0 + row) * CONVDIM
                                 + DINNER + DSTATE + col);
    sC[o] = vc.x; sC[o + 1] = vc.y; sC[o + 2] = vc.z; sC[o + 3] = vc.w;
  }
  if (tid < 64) scl[tid] = g_cl[bh * SEQLEN + t0 + tid];
  __syncthreads();

  const int tr = (tid >> 4) << 2;
  const int pc = (tid & 15) << 2;
  float acc[4][4];
  #pragma unroll
  for (int i = 0; i < 4; i++)
    #pragma unroll
    for (int j = 0; j < 4; j++) acc[i][j] = 0.f;
  for (int n = 0; n < 64; ++n) {
    float cf[4], sf[4];
    #pragma unroll
    for (int i = 0; i < 4; i++) cf[i] = sC[(tr + i) * 65 + n];
    #pragma unroll
    for (int j = 0; j < 4; j++) sf[j] = sS[(pc + j) * 65 + n];
    #pragma unroll
    for (int i = 0; i < 4; i++)
      #pragma unroll
      for (int j = 0; j < 4; j++) acc[i][j] += cf[i] * sf[j];
  }
  #pragma unroll
  for (int i = 0; i < 4; i++) {
    float e = __expf(scl[tr + i]);
    size_t o = (size_t)(b * SEQLEN + t0 + tr + i) * DINNER + h * HD + pc;
    float4 cur = *(float4*)(g_y + o);
    cur.x += e * acc[i][0]; cur.y += e * acc[i][1];
    cur.z += e * acc[i][2]; cur.w += e * acc[i][3];
    *(float4*)(g_y + o) = cur;
  }
}

// ---------------- gate + RMSNorm, emits bf16 hi/lo split --------------------
__global__ __launch_bounds__(256) void norm_kernel(const float* __restrict__ nw) {
  const int pos = blockIdx.x, tid = threadIdx.x;
  float4 yv = *(const float4*)(g_y  + (size_t)pos * DINNER + tid * 4);
  float4 zv = *(const float4*)(g_zx + (size_t)pos * DPROJ  + tid * 4);
  float4 g;
  g.x = yv.x * (zv.x / (1.f + __expf(-zv.x)));
  g.y = yv.y * (zv.y / (1.f + __expf(-zv.y)));
  g.z = yv.z * (zv.z / (1.f + __expf(-zv.z)));
  g.w = yv.w * (zv.w / (1.f + __expf(-zv.w)));
  float ssq = g.x * g.x + g.y * g.y + g.z * g.z + g.w * g.w;
  #pragma unroll
  for (int o = 16; o; o >>= 1) ssq += __shfl_xor_sync(0xFFFFFFFFu, ssq, o);
  __shared__ float red[8];
  if ((tid & 31) == 0) red[tid >> 5] = ssq;
  __syncthreads();
  float tot = red[0] + red[1] + red[2] + red[3] + red[4] + red[5] + red[6] + red[7];
  float scale = rsqrtf(tot * (1.f / DINNER) + EPSV);
  float4 w = *(const float4*)(nw + tid * 4);
  float o0 = g.x * scale * w.x, o1 = g.y * scale * w.y;
  float o2 = g.z * scale * w.z, o3 = g.w * scale * w.w;
  size_t base = (size_t)pos * DINNER + tid * 4;
  __nv_bfloat16 h0 = __float2bfloat16(o0), h1 = __float2bfloat16(o1);
  __nv_bfloat16 h2 = __float2bfloat16(o2), h3 = __float2bfloat16(o3);
  g_yh[base + 0] = h0; g_yh[base + 1] = h1; g_yh[base + 2] = h2; g_yh[base + 3] = h3;
  g_yl[base + 0] = __float2bfloat16(o0 - __bfloat162float(h0));
  g_yl[base + 1] = __float2bfloat16(o1 - __bfloat162float(h1));
  g_yl[base + 2] = __float2bfloat16(o2 - __bfloat162float(h2));
  g_yl[base + 3] = __float2bfloat16(o3 - __bfloat162float(h3));
}

// ---------------- launch ------------------------------------------------------
extern "C" void kernel_launch(void* const* d_in, const int* in_sizes, int n_in,
                              void* d_out, int out_size) {
  const float* x       = (const float*)d_in[0];
  const float* W_in    = (const float*)d_in[1];
  const float* conv_w  = (const float*)d_in[2];
  const float* conv_b  = (const float*)d_in[3];
  const float* dt_bias = (const float*)d_in[4];
  const float* A_log   = (const float*)d_in[5];
  const float* Dv      = (const float*)d_in[6];
  const float* nw      = (const float*)d_in[7];
  const float* W_out   = (const float*)d_in[8];
  float* out = (float*)d_out;

  void* p;
  cudaGetSymbolAddress(&p, g_zx);  float* zx = (float*)p;
  cudaGetSymbolAddress(&p, g_xh);  __nv_bfloat16* xh  = (__nv_bfloat16*)p;
  cudaGetSymbolAddress(&p, g_xl);  __nv_bfloat16* xl  = (__nv_bfloat16*)p;
  cudaGetSymbolAddress(&p, g_w1h); __nv_bfloat16* w1h = (__nv_bfloat16*)p;
  cudaGetSymbolAddress(&p, g_w1l); __nv_bfloat16* w1l = (__nv_bfloat16*)p;
  cudaGetSymbolAddress(&p, g_yh);  __nv_bfloat16* yh  = (__nv_bfloat16*)p;
  cudaGetSymbolAddress(&p, g_yl);  __nv_bfloat16* yl  = (__nv_bfloat16*)p;
  cudaGetSymbolAddress(&p, g_w2h); __nv_bfloat16* w2h = (__nv_bfloat16*)p;
  cudaGetSymbolAddress(&p, g_w2l); __nv_bfloat16* w2l = (__nv_bfloat16*)p;

  cudaFuncSetAttribute(chunk_kernel, cudaFuncAttributeMaxDynamicSharedMemorySize, 67072);
  cudaFuncSetAttribute(gemm_tc, cudaFuncAttributeMaxDynamicSharedMemorySize, SM_TOTAL);

  dim3 blk(256);
  // operand prep for GEMM1
  split_kernel<<<(NPOS * DMODEL) / 256, blk>>>(x, xh, xl, NPOS * DMODEL);
  wtrans_kernel<<<dim3(NPAD1 / 32, DMODEL / 32), dim3(32, 8)>>>(W_in, w1h, w1l, DMODEL, DPROJ);
  // 1) in-projection (HMMA tensor cores): zx = x @ W_in
  gemm_tc<<<dim3(NPAD1 / 128, NPOS / 128), blk, SM_TOTAL>>>(xh, xl, w1h, w1l, zx,
                                                            DMODEL, DPROJ, DPROJ);
  // 2) conv + silu
  conv_kernel<<<(unsigned)(((size_t)NPOS * CONVDIM + 255) / 256), blk>>>(conv_w, conv_b);
  // 3) dt
  dt_kernel<<<(NPOS * NH) / 256, blk>>>(dt_bias, A_log);
  // 4) cumlog
  cumlog_kernel<<<(BATCH * NH * NC * 32) / 256, blk>>>();
  // 5) intra-chunk SSD
  chunk_kernel<<<BATCH * NH * NC, blk, 67072>>>(Dv);
  // 6) inter-chunk state scan (widened)
  scan_kernel<<<dim3(BATCH * NH, 8), dim3(128)>>>();
  // 7) inter-chunk correction
  inter_kernel<<<BATCH * NH * NC, blk>>>();
  // 8) gate + RMSNorm (emits bf16 splits)
  norm_kernel<<<NPOS, blk>>>(nw);
  // operand prep for GEMM2
  wtrans_kernel<<<dim3(DMODEL / 32, DINNER / 32), dim3(32, 8)>>>(W_out, w2h, w2l, DINNER, DMODEL);
  // 9) out-projection (HMMA tensor cores)
  gemm_tc<<<dim3(DMODEL / 128, NPOS / 128), blk, SM_TOTAL>>>(yh, yl, w2h, w2l, out,
                                                             DINNER, DMODEL, DMODEL);
}

// round 4
// speedup vs baseline: 3.1487x; 1.5114x over previous
#include <cuda_runtime.h>
#include <cuda_fp16.h>
#include <cstdint>
#include <cstddef>

#define BATCH   2
#define SEQLEN  4096
#define DMODEL  512
#define DINNER  1024
#define NH      16
#define HD      64
#define DSTATE  64
#define CONVDIM 1152
#define DPROJ   2192
#define NPOS    (BATCH * SEQLEN)   // 8192
#define NC      64
#define CS      64
#define EPSV    1e-5f
#define NPAD1   2304               // 18*128 padded N for GEMM1

// ---------------- scratch (static device globals) ---------------------------
__device__ float g_zx [(size_t)NPOS * DPROJ];
__device__ float g_xbc[(size_t)NPOS * CONVDIM];
__device__ float g_dt [NPOS * NH];
__device__ float g_la [NPOS * NH];
__device__ float g_cl [BATCH * NH * SEQLEN];
__device__ float g_S  [(size_t)BATCH * NH * NC * HD * DSTATE];
__device__ float g_y  [(size_t)NPOS * DINNER];

// fp16 operands for tensor-core GEMMs (single-pass)
__device__ __half g_xh [(size_t)NPOS * DMODEL];
__device__ __half g_w1h[(size_t)NPAD1 * DMODEL];
__device__ __half g_yh [(size_t)NPOS * DINNER];
__device__ __half g_w2h[(size_t)DMODEL * DINNER];

// ---------------- PTX helpers (portable sm_80+ subset only) -----------------
__device__ __forceinline__ uint32_t smem_u32(const void* p) {
  uint32_t a;
  asm("{ .reg .u64 t; cvta.to.shared.u64 t, %1; cvt.u32.u64 %0, t; }" : "=r"(a) : "l"(p));
  return a;
}
__device__ __forceinline__ void ldm4(uint32_t* r, uint32_t addr) {
  asm volatile("ldmatrix.sync.aligned.m8n8.x4.shared.b16 {%0,%1,%2,%3}, [%4];"
               : "=r"(r[0]), "=r"(r[1]), "=r"(r[2]), "=r"(r[3]) : "r"(addr));
}
__device__ __forceinline__ void mma16816(float* c, const uint32_t* a, const uint32_t* b) {
  asm volatile(
      "mma.sync.aligned.m16n8k16.row.col.f32.f16.f16.f32 "
      "{%0,%1,%2,%3}, {%4,%5,%6,%7}, {%8,%9}, {%0,%1,%2,%3};"
      : "+f"(c[0]), "+f"(c[1]), "+f"(c[2]), "+f"(c[3])
      : "r"(a[0]), "r"(a[1]), "r"(a[2]), "r"(a[3]), "r"(b[0]), "r"(b[1]));
}
#define CPASYNC(dst, src) \
  asm volatile("cp.async.cg.shared.global [%0], [%1], 16;" :: "r"(dst), "l"(src))
#define CPCOMMIT() asm volatile("cp.async.commit_group;" ::: "memory")
#define CPWAIT(n)  asm volatile("cp.async.wait_group %0;" :: "n"(n) : "memory")
#define SWZ(off)   ((off) ^ (((off) >> 3) & 0x70))

// ---------------- HMMA GEMM (fp16 single pass): C = A @ B^T -----------------
// A[M][K] K-major fp16; B[Npad][K] K-major fp16; C fp32 (predicated col<N).
// CTA tile 128x128, K-chunk 64, cp.async double buffer, 8 warps (64x32 each).
#define SM_BUF   32768           // 2 tiles x 128 rows x 128B
#define SM_TOTAL (2 * SM_BUF)

__global__ __launch_bounds__(256, 2) void gemm_tc(
    const __half* __restrict__ A, const __half* __restrict__ B,
    float* __restrict__ C, int K, int N, int ldc) {
  extern __shared__ char smem[];
  const uint32_t sb = smem_u32(smem);
  const int tid = threadIdx.x, wid = tid >> 5, lane = tid & 31;
  const int bm = blockIdx.y * 128, bn = blockIdx.x * 128;
  const int wrow = wid & 1, wcol = wid >> 1;          // warp tile: 64(M) x 32(N)

  float acc[4][4][4];
  #pragma unroll
  for (int i = 0; i < 4; i++)
    #pragma unroll
    for (int j = 0; j < 4; j++)
      #pragma unroll
      for (int v = 0; v < 4; v++) acc[i][j][v] = 0.f;

  const int nK = K >> 6;

  // prologue: chunk 0 -> buf 0   (8 x 16B per thread per chunk)
  {
    #pragma unroll
    for (int it = 0; it < 8; it++) {
      const int u = it * 256 + tid;
      const int tile = u >> 10, idx = u & 1023;
      const int row = idx >> 3, c16 = idx & 7;
      const uint32_t dst = sb + tile * 16384 + SWZ((uint32_t)(row * 128 + c16 * 16));
      const __half* src = (tile == 0) ? A + (size_t)(bm + row) * K + c16 * 8
                                      : B + (size_t)(bn + row) * K + c16 * 8;
      CPASYNC(dst, src);
    }
    CPCOMMIT();
  }

  for (int i = 0; i < nK; i++) {
    if (i + 1 < nK) {
      const int k0 = (i + 1) << 6;
      const uint32_t bbuf = sb + ((i + 1) & 1) * SM_BUF;
      #pragma unroll
      for (int it = 0; it < 8; it++) {
        const int u = it * 256 + tid;
        const int tile = u >> 10, idx = u & 1023;
        const int row = idx >> 3, c16 = idx & 7;
        const uint32_t dst = bbuf + tile * 16384 + SWZ((uint32_t)(row * 128 + c16 * 16));
        const __half* src = (tile == 0) ? A + (size_t)(bm + row) * K + k0 + c16 * 8
                                        : B + (size_t)(bn + row) * K + k0 + c16 * 8;
        CPASYNC(dst, src);
      }
      CPCOMMIT();
      CPWAIT(1);
    } else {
      CPWAIT(0);
    }
    __syncthreads();

    const uint32_t tb = sb + (i & 1) * SM_BUF;
    const int arow = wrow * 64 + (lane & 15);
    const int brow = wcol * 32 + (lane & 7) + ((lane >> 4) & 1) * 8;
    const int akb  = (lane >> 4) * 16;
    const int bkb  = ((lane >> 3) & 1) * 16;

    #pragma unroll
    for (int ks = 0; ks < 4; ks++) {
      uint32_t ah[4][4], bh[2][4];
      #pragma unroll
      for (int mt = 0; mt < 4; mt++) {
        const uint32_t off = SWZ((uint32_t)((arow + mt * 16) * 128 + ks * 32 + akb));
        ldm4(ah[mt], tb + off);
      }
      #pragma unroll
      for (int p = 0; p < 2; p++) {
        const uint32_t off = SWZ((uint32_t)((brow + p * 16) * 128 + ks * 32 + bkb));
        ldm4(bh[p], tb + 16384 + off);
      }
      #pragma unroll
      for (int mt = 0; mt < 4; mt++)
        #pragma unroll
        for (int p = 0; p < 2; p++) {
          mma16816(acc[mt][2 * p],     ah[mt], &bh[p][0]);
          mma16816(acc[mt][2 * p + 1], ah[mt], &bh[p][2]);
        }
    }
    __syncthreads();
  }

  const int r0 = bm + wrow * 64 + (lane >> 2);
  const int c0 = bn + wcol * 32 + (lane & 3) * 2;
  #pragma unroll
  for (int mt = 0; mt < 4; mt++)
    #pragma unroll
    for (int nt = 0; nt < 4; nt++) {
      const int col = c0 + nt * 8;
      if (col < N) {
        const int row = r0 + mt * 16;
        *(float2*)&C[(size_t)row * ldc + col] =
            make_float2(acc[mt][nt][0], acc[mt][nt][1]);
        *(float2*)&C[(size_t)(row + 8) * ldc + col] =
            make_float2(acc[mt][nt][2], acc[mt][nt][3]);
      }
    }
}

// ---------------- fp32 -> fp16 cast ------------------------------------------
__global__ void tofp16_kernel(const float* __restrict__ src,
                              __half* __restrict__ dst, int n) {
  int i = blockIdx.x * 256 + threadIdx.x;
  if (i < n) dst[i] = __float2half(src[i]);
}

// ---------------- W transpose -> fp16: out[n][k] = W[k][n] -------------------
__global__ void wtrans_kernel(const float* __restrict__ W,
                              __half* __restrict__ th, int K, int N) {
  __shared__ float t[32][33];
  const int n0 = blockIdx.x * 32, k0 = blockIdx.y * 32;
  const int tx = threadIdx.x, ty = threadIdx.y;
  #pragma unroll
  for (int r = 0; r < 4; r++) {
    int k = k0 + ty + r * 8, n = n0 + tx;
    t[ty + r * 8][tx] = (n < N) ? W[(size_t)k * N + n] : 0.f;
  }
  __syncthreads();
  #pragma unroll
  for (int r = 0; r < 4; r++) {
    int n = n0 + ty + r * 8, k = k0 + tx;
    th[(size_t)n * K + k] = __float2half(t[tx][ty + r * 8]);
  }
}

// ---------------- depthwise causal conv + bias + SiLU (8 steps/thread) ------
__global__ __launch_bounds__(128) void conv_kernel(const float* __restrict__ cw,
                                                   const float* __restrict__ cb) {
  const int ch  = blockIdx.x * 128 + threadIdx.x;     // 9 x 128 = 1152
  const int grp = blockIdx.y;                         // 0..1023, 8 steps each
  const size_t pos0 = (size_t)grp * 8;
  const int l0 = (int)(pos0 & (SEQLEN - 1));
  const float* src = g_zx + pos0 * DPROJ + DINNER + ch;
  const float w0 = cw[ch * 4 + 0], w1 = cw[ch * 4 + 1];
  const float w2 = cw[ch * 4 + 2], w3 = cw[ch * 4 + 3];
  const float bias = cb[ch];
  float v[11];
  #pragma unroll
  for (int j = 0; j < 3; j++)
    v[j] = (l0 >= 3 - j) ? src[(ptrdiff_t)(j - 3) * DPROJ] : 0.f;
  #pragma unroll
  for (int j = 0; j < 8; j++)
    v[3 + j] = src[(ptrdiff_t)j * DPROJ];
  float* dst = g_xbc + pos0 * CONVDIM + ch;
  #pragma unroll
  for (int j = 0; j < 8; j++) {
    float a = bias + w0 * v[j] + w1 * v[j + 1] + w2 * v[j + 2] + w3 * v[j + 3];
    dst[(size_t)j * CONVDIM] = a / (1.f + __expf(-a));
  }
}

// ---------------- dt softplus + log-decay -----------------------------------
__global__ void dt_kernel(const float* __restrict__ dtb, const float* __restrict__ alog) {
  int idx = blockIdx.x * 256 + threadIdx.x;
  int h = idx & (NH - 1);
  int pos = idx >> 4;
  float v = g_zx[(size_t)pos * DPROJ + DINNER + CONVDIM + h] + dtb[h];
  float sp = (v > 20.f) ? v : log1pf(expf(v));
  g_dt[idx] = sp;
  g_la[idx] = -expf(alog[h]) * sp;
}

// ---------------- per-chunk inclusive cumsum (one warp per chunk) -----------
__global__ void cumlog_kernel() {
  const int gw = (blockIdx.x * 256 + threadIdx.x) >> 5;
  const int lane = threadIdx.x & 31;
  const int c = gw & (NC - 1);
  const int bh = gw >> 6;
  const int b = bh >> 4, h = bh & (NH - 1);
  const int t0 = c * CS;
  float x0 = g_la[((b * SEQLEN + t0 + lane) << 4) + h];
  float x1 = g_la[((b * SEQLEN + t0 + 32 + lane) << 4) + h];
  #pragma unroll
  for (int o = 1; o < 32; o <<= 1) {
    float v = __shfl_up_sync(0xFFFFFFFFu, x0, o);
    if (lane >= o) x0 += v;
  }
  float tot0 = __shfl_sync(0xFFFFFFFFu, x0, 31);
  #pragma unroll
  for (int o = 1; o < 32; o <<= 1) {
    float v = __shfl_up_sync(0xFFFFFFFFu, x1, o);
    if (lane >= o) x1 += v;
  }
  x1 += tot0;
  g_cl[bh * SEQLEN + t0 + lane] = x0;
  g_cl[bh * SEQLEN + t0 + 32 + lane] = x1;
}

// ---------------- intra-chunk SSD kernel -------------------------------------
__global__ __launch_bounds__(256) void chunk_kernel(const float* __restrict__ Dv) {
  extern __shared__ float sm[];
  float* sB  = sm;
  float* sCX = sm + 4160;
  float* sX  = sm + 8320;
  float* sM  = sm + 12480;
  float* scl = sm + 16640;
  float* sdt = sm + 16704;

  const int bid = blockIdx.x;
  const int c = bid & (NC - 1);
  const int bh = bid >> 6;
  const int h = bh & (NH - 1);
  const int b = bh >> 4;
  const int tid = threadIdx.x;
  const int t0 = c * CS;

  for (int i = tid; i < 1024; i += 256) {
    int row = i >> 4, col = (i & 15) << 2;
    const float* base = g_xbc + (size_t)(b * SEQLEN + t0 + row) * CONVDIM;
    float4 vb = *(const float4*)(base + DINNER + col);
    float4 vc = *(const float4*)(base + DINNER + DSTATE + col);
    float4 vx = *(const float4*)(base + h * HD + col);
    int o = row * 65 + col;
    sB [o] = vb.x; sB [o + 1] = vb.y; sB [o + 2] = vb.z; sB [o + 3] = vb.w;
    sCX[o] = vc.x; sCX[o + 1] = vc.y; sCX[o + 2] = vc.z; sCX[o + 3] = vc.w;
    sX [o] = vx.x; sX [o + 1] = vx.y; sX [o + 2] = vx.z; sX [o + 3] = vx.w;
  }
  if (tid < 64) {
    scl[tid] = g_cl[bh * SEQLEN + t0 + tid];
    sdt[tid] = g_dt[(b * SEQLEN + t0 + tid) * NH + h];
  }
  __syncthreads();

  const int tr = (tid >> 4) << 2;
  const int sc = (tid & 15) << 2;

  float mm[4][4];
  #pragma unroll
  for (int i = 0; i < 4; i++)
    #pragma unroll
    for (int j = 0; j < 4; j++) mm[i][j] = 0.f;
  for (int n = 0; n < 64; ++n) {
    float cf[4], bf[4];
    #pragma unroll
    for (int i = 0; i < 4; i++) cf[i] = sCX[(tr + i) * 65 + n];
    #pragma unroll
    for (int j = 0; j < 4; j++) bf[j] = sB[(sc + j) * 65 + n];
    #pragma unroll
    for (int i = 0; i < 4; i++)
      #pragma unroll
      for (int j = 0; j < 4; j++) mm[i][j] += cf[i] * bf[j];
  }
  const float Ltot = scl[63];
  #pragma unroll
  for (int i = 0; i < 4; i++)
    #pragma unroll
    for (int j = 0; j < 4; j++) {
      int t = tr + i, s = sc + j;
      mm[i][j] = (s <= t) ? mm[i][j] * __expf(scl[t] - scl[s]) * sdt[s] : 0.f;
    }
  __syncthreads();

  #pragma unroll
  for (int i = 0; i < 4; i++)
    #pragma unroll
    for (int j = 0; j < 4; j++) sM[(tr + i) * 65 + sc + j] = mm[i][j];
  for (int i = tid; i < 1024; i += 256) {
    int row = i >> 4, col = (i & 15) << 2;
    float w = __expf(Ltot - scl[row]) * sdt[row];
    int o = row * 65 + col;
    sCX[o]     = w * sX[o];
    sCX[o + 1] = w * sX[o + 1];
    sCX[o + 2] = w * sX[o + 2];
    sCX[o + 3] = w * sX[o + 3];
  }
  __syncthreads();

  float yy[4][4], ss[4][4];
  #pragma unroll
  for (int i = 0; i < 4; i++)
    #pragma unroll
    for (int j = 0; j < 4; j++) { yy[i][j] = 0.f; ss[i][j] = 0.f; }
  for (int k = 0; k < 64; ++k) {
    float mv[4], xw[4], xv[4], bn[4];
    #pragma unroll
    for (int i = 0; i < 4; i++) {
      mv[i] = sM[(tr + i) * 65 + k];
      xw[i] = sCX[k * 65 + tr + i];
    }
    #pragma unroll
    for (int j = 0; j < 4; j++) {
      xv[j] = sX[k * 65 + sc + j];
      bn[j] = sB[k * 65 + sc + j];
    }
    #pragma unroll
    for (int i = 0; i < 4; i++)
      #pragma unroll
      for (int j = 0; j < 4; j++) {
        yy[i][j] += mv[i] * xv[j];
        ss[i][j] += xw[i] * bn[j];
      }
  }

  const float Dh = Dv[h];
  #pragma unroll
  for (int i = 0; i < 4; i++) {
    float4 o4;
    o4.x = yy[i][0] + Dh * sX[(tr + i) * 65 + sc + 0];
    o4.y = yy[i][1] + Dh * sX[(tr + i) * 65 + sc + 1];
    o4.z = yy[i][2] + Dh * sX[(tr + i) * 65 + sc + 2];
    o4.w = yy[i][3] + Dh * sX[(tr + i) * 65 + sc + 3];
    *(float4*)(g_y + (size_t)(b * SEQLEN + t0 + tr + i) * DINNER + h * HD + sc) = o4;
    float4 s4 = make_float4(ss[i][0], ss[i][1], ss[i][2], ss[i][3]);
    *(float4*)(g_S + (size_t)bid * 4096 + (tr + i) * 64 + sc) = s4;
  }
}

// ---------------- inter-chunk state scan (32 x 8 blocks) --------------------
__global__ __launch_bounds__(128) void scan_kernel() {
  const int bh = blockIdx.x;
  const int slice = blockIdx.y;
  const int tid = threadIdx.x;
  const int off = slice * 512 + tid * 4;
  float run[4] = {0.f, 0.f, 0.f, 0.f};
  for (int c = 0; c < NC; c++) {
    float a = __expf(g_cl[bh * SEQLEN + c * CS + CS - 1]);
    float* p = g_S + (size_t)(bh * NC + c) * 4096 + off;
    float4 v = *(float4*)p;
    *(float4*)p = make_float4(run[0], run[1], run[2], run[3]);
    run[0] = a * run[0] + v.x;
    run[1] = a * run[1] + v.y;
    run[2] = a * run[2] + v.z;
    run[3] = a * run[3] + v.w;
  }
}

// ---------------- inter-chunk contribution -----------------------------------
__global__ __launch_bounds__(256) void inter_kernel() {
  __shared__ float sS[4160];
  __shared__ float sC[4160];
  __shared__ float scl[64];
  const int bid = blockIdx.x;
  const int c = bid & (NC - 1);
  const int bh = bid >> 6;
  const int h = bh & (NH - 1);
  const int b = bh >> 4;
  const int tid = threadIdx.x;
  const int t0 = c * CS;

  for (int i = tid; i < 1024; i += 256) {
    int row = i >> 4, col = (i & 15) << 2;
    float4 v = *(const float4*)(g_S + (size_t)bid * 4096 + row * 64 + col);
    int o = row * 65 + col;
    sS[o] = v.x; sS[o + 1] = v.y; sS[o + 2] = v.z; sS[o + 3] = v.w;
    float4 vc = *(const float4*)(g_xbc + (size_t)(b * SEQLEN + t0 + row) * CONVDIM
                                 + DINNER + DSTATE + col);
    sC[o] = vc.x; sC[o + 1] = vc.y; sC[o + 2] = vc.z; sC[o + 3] = vc.w;
  }
  if (tid < 64) scl[tid] = g_cl[bh * SEQLEN + t0 + tid];
  __syncthreads();

  const int tr = (tid >> 4) << 2;
  const int pc = (tid & 15) << 2;
  float acc[4][4];
  #pragma unroll
  for (int i = 0; i < 4; i++)
    #pragma unroll
    for (int j = 0; j < 4; j++) acc[i][j] = 0.f;
  for (int n = 0; n < 64; ++n) {
    float cf[4], sf[4];
    #pragma unroll
    for (int i = 0; i < 4; i++) cf[i] = sC[(tr + i) * 65 + n];
    #pragma unroll
    for (int j = 0; j < 4; j++) sf[j] = sS[(pc + j) * 65 + n];
    #pragma unroll
    for (int i = 0; i < 4; i++)
      #pragma unroll
      for (int j = 0; j < 4; j++) acc[i][j] += cf[i] * sf[j];
  }
  #pragma unroll
  for (int i = 0; i < 4; i++) {
    float e = __expf(scl[tr + i]);
    size_t o = (size_t)(b * SEQLEN + t0 + tr + i) * DINNER + h * HD + pc;
    float4 cur = *(float4*)(g_y + o);
    cur.x += e * acc[i][0]; cur.y += e * acc[i][1];
    cur.z += e * acc[i][2]; cur.w += e * acc[i][3];
    *(float4*)(g_y + o) = cur;
  }
}

// ---------------- gate + RMSNorm, emits fp16 ---------------------------------
__global__ __launch_bounds__(256) void norm_kernel(const float* __restrict__ nw) {
  const int pos = blockIdx.x, tid = threadIdx.x;
  float4 yv = *(const float4*)(g_y  + (size_t)pos * DINNER + tid * 4);
  float4 zv = *(const float4*)(g_zx + (size_t)pos * DPROJ  + tid * 4);
  float4 g;
  g.x = yv.x * (zv.x / (1.f + __expf(-zv.x)));
  g.y = yv.y * (zv.y / (1.f + __expf(-zv.y)));
  g.z = yv.z * (zv.z / (1.f + __expf(-zv.z)));
  g.w = yv.w * (zv.w / (1.f + __expf(-zv.w)));
  float ssq = g.x * g.x + g.y * g.y + g.z * g.z + g.w * g.w;
  #pragma unroll
  for (int o = 16; o; o >>= 1) ssq += __shfl_xor_sync(0xFFFFFFFFu, ssq, o);
  __shared__ float red[8];
  if ((tid & 31) == 0) red[tid >> 5] = ssq;
  __syncthreads();
  float tot = red[0] + red[1] + red[2] + red[3] + red[4] + red[5] + red[6] + red[7];
  float scale = rsqrtf(tot * (1.f / DINNER) + EPSV);
  float4 w = *(const float4*)(nw + tid * 4);
  __half2* dst = (__half2*)(g_yh + (size_t)pos * DINNER + tid * 4);
  dst[0] = __floats2half2_rn(g.x * scale * w.x, g.y * scale * w.y);
  dst[1] = __floats2half2_rn(g.z * scale * w.z, g.w * scale * w.w);
}

// ---------------- launch ------------------------------------------------------
extern "C" void kernel_launch(void* const* d_in, const int* in_sizes, int n_in,
                              void* d_out, int out_size) {
  const float* x       = (const float*)d_in[0];
  const float* W_in    = (const float*)d_in[1];
  const float* conv_w  = (const float*)d_in[2];
  const float* conv_b  = (const float*)d_in[3];
  const float* dt_bias = (const float*)d_in[4];
  const float* A_log   = (const float*)d_in[5];
  const float* Dv      = (const float*)d_in[6];
  const float* nw      = (const float*)d_in[7];
  const float* W_out   = (const float*)d_in[8];
  float* out = (float*)d_out;

  void* p;
  cudaGetSymbolAddress(&p, g_zx);  float* zx = (float*)p;
  cudaGetSymbolAddress(&p, g_xh);  __half* xh  = (__half*)p;
  cudaGetSymbolAddress(&p, g_w1h); __half* w1h = (__half*)p;
  cudaGetSymbolAddress(&p, g_yh);  __half* yh  = (__half*)p;
  cudaGetSymbolAddress(&p, g_w2h); __half* w2h = (__half*)p;

  cudaFuncSetAttribute(chunk_kernel, cudaFuncAttributeMaxDynamicSharedMemorySize, 67072);
  cudaFuncSetAttribute(gemm_tc, cudaFuncAttributeMaxDynamicSharedMemorySize, SM_TOTAL);

  dim3 blk(256);
  // operand prep (wtrans2 early: independent, and puts gemm1 at launch #4 for ncu)
  tofp16_kernel<<<(NPOS * DMODEL) / 256, blk>>>(x, xh, NPOS * DMODEL);
  wtrans_kernel<<<dim3(NPAD1 / 32, DMODEL / 32), dim3(32, 8)>>>(W_in, w1h, DMODEL, DPROJ);
  wtrans_kernel<<<dim3(DMODEL / 32, DINNER / 32), dim3(32, 8)>>>(W_out, w2h, DINNER, DMODEL);
  // 1) in-projection (fp16 HMMA): zx = x @ W_in
  gemm_tc<<<dim3(NPAD1 / 128, NPOS / 128), blk, SM_TOTAL>>>(xh, w1h, zx,
                                                            DMODEL, DPROJ, DPROJ);
  // 2) conv + silu (8 timesteps/thread)
  conv_kernel<<<dim3(CONVDIM / 128, NPOS / 8), dim3(128)>>>(conv_w, conv_b);
  // 3) dt
  dt_kernel<<<(NPOS * NH) / 256, blk>>>(dt_bias, A_log);
  // 4) cumlog
  cumlog_kernel<<<(BATCH * NH * NC * 32) / 256, blk>>>();
  // 5) intra-chunk SSD
  chunk_kernel<<<BATCH * NH * NC, blk, 67072>>>(Dv);
  // 6) inter-chunk state scan
  scan_kernel<<<dim3(BATCH * NH, 8), dim3(128)>>>();
  // 7) inter-chunk correction
  inter_kernel<<<BATCH * NH * NC, blk>>>();
  // 8) gate + RMSNorm (emits fp16)
  norm_kernel<<<NPOS, blk>>>(nw);
  // 9) out-projection (fp16 HMMA)
  gemm_tc<<<dim3(DMODEL / 128, NPOS / 128), blk, SM_TOTAL>>>(yh, w2h, out,
                                                             DINNER, DMODEL, DMODEL);
}

// round 5
// speedup vs baseline: 3.9914x; 1.2677x over previous
#include <cuda_runtime.h>
#include <cuda_fp16.h>
#include <cstdint>
#include <cstddef>

#define BATCH   2
#define SEQLEN  4096
#define DMODEL  512
#define DINNER  1024
#define NH      16
#define HD      64
#define DSTATE  64
#define CONVDIM 1152
#define DPROJ   2192
#define NPOS    (BATCH * SEQLEN)   // 8192
#define NC      64
#define CS      64
#define EPSV    1e-5f
#define NPAD1   2304               // 18*128 padded N for GEMM1

// ---------------- scratch (static device globals) ---------------------------
__device__ float g_zx [(size_t)NPOS * DPROJ];
__device__ float g_xbc[(size_t)NPOS * CONVDIM];
__device__ float g_dt [NPOS * NH];
__device__ float g_la [NPOS * NH];
__device__ float g_cl [BATCH * NH * SEQLEN];
__device__ float g_S  [(size_t)BATCH * NH * NC * HD * DSTATE];
__device__ float g_y  [(size_t)NPOS * DINNER];

// fp16 operands for tensor-core GEMMs (single-pass)
__device__ __half g_xh [(size_t)NPOS * DMODEL];
__device__ __half g_w1h[(size_t)NPAD1 * DMODEL];
__device__ __half g_yh [(size_t)NPOS * DINNER];
__device__ __half g_w2h[(size_t)DMODEL * DINNER];

// ---------------- PTX helpers (portable sm_80+ subset only) -----------------
__device__ __forceinline__ uint32_t smem_u32(const void* p) {
  uint32_t a;
  asm("{ .reg .u64 t; cvta.to.shared.u64 t, %1; cvt.u32.u64 %0, t; }" : "=r"(a) : "l"(p));
  return a;
}
__device__ __forceinline__ void ldm4(uint32_t* r, uint32_t addr) {
  asm volatile("ldmatrix.sync.aligned.m8n8.x4.shared.b16 {%0,%1,%2,%3}, [%4];"
               : "=r"(r[0]), "=r"(r[1]), "=r"(r[2]), "=r"(r[3]) : "r"(addr));
}
__device__ __forceinline__ void mma16816(float* c, const uint32_t* a, const uint32_t* b) {
  asm volatile(
      "mma.sync.aligned.m16n8k16.row.col.f32.f16.f16.f32 "
      "{%0,%1,%2,%3}, {%4,%5,%6,%7}, {%8,%9}, {%0,%1,%2,%3};"
      : "+f"(c[0]), "+f"(c[1]), "+f"(c[2]), "+f"(c[3])
      : "r"(a[0]), "r"(a[1]), "r"(a[2]), "r"(a[3]), "r"(b[0]), "r"(b[1]));
}
#define CPASYNC(dst, src) \
  asm volatile("cp.async.cg.shared.global [%0], [%1], 16;" :: "r"(dst), "l"(src))
#define CPCOMMIT() asm volatile("cp.async.commit_group;" ::: "memory")
#define CPWAIT(n)  asm volatile("cp.async.wait_group %0;" :: "n"(n) : "memory")
#define SWZ(off)   ((off) ^ (((off) >> 3) & 0x70))

// ---------------- HMMA GEMM (fp16 single pass): C = A @ B^T -----------------
#define SM_BUF   32768
#define SM_TOTAL (2 * SM_BUF)

__global__ __launch_bounds__(256, 2) void gemm_tc(
    const __half* __restrict__ A, const __half* __restrict__ B,
    float* __restrict__ C, int K, int N, int ldc) {
  extern __shared__ char smem[];
  const uint32_t sb = smem_u32(smem);
  const int tid = threadIdx.x, wid = tid >> 5, lane = tid & 31;
  const int bm = blockIdx.y * 128, bn = blockIdx.x * 128;
  const int wrow = wid & 1, wcol = wid >> 1;

  float acc[4][4][4];
  #pragma unroll
  for (int i = 0; i < 4; i++)
    #pragma unroll
    for (int j = 0; j < 4; j++)
      #pragma unroll
      for (int v = 0; v < 4; v++) acc[i][j][v] = 0.f;

  const int nK = K >> 6;
  {
    #pragma unroll
    for (int it = 0; it < 8; it++) {
      const int u = it * 256 + tid;
      const int tile = u >> 10, idx = u & 1023;
      const int row = idx >> 3, c16 = idx & 7;
      const uint32_t dst = sb + tile * 16384 + SWZ((uint32_t)(row * 128 + c16 * 16));
      const __half* src = (tile == 0) ? A + (size_t)(bm + row) * K + c16 * 8
                                      : B + (size_t)(bn + row) * K + c16 * 8;
      CPASYNC(dst, src);
    }
    CPCOMMIT();
  }

  for (int i = 0; i < nK; i++) {
    if (i + 1 < nK) {
      const int k0 = (i + 1) << 6;
      const uint32_t bbuf = sb + ((i + 1) & 1) * SM_BUF;
      #pragma unroll
      for (int it = 0; it < 8; it++) {
        const int u = it * 256 + tid;
        const int tile = u >> 10, idx = u & 1023;
        const int row = idx >> 3, c16 = idx & 7;
        const uint32_t dst = bbuf + tile * 16384 + SWZ((uint32_t)(row * 128 + c16 * 16));
        const __half* src = (tile == 0) ? A + (size_t)(bm + row) * K + k0 + c16 * 8
                                        : B + (size_t)(bn + row) * K + k0 + c16 * 8;
        CPASYNC(dst, src);
      }
      CPCOMMIT();
      CPWAIT(1);
    } else {
      CPWAIT(0);
    }
    __syncthreads();

    const uint32_t tb = sb + (i & 1) * SM_BUF;
    const int arow = wrow * 64 + (lane & 15);
    const int brow = wcol * 32 + (lane & 7) + ((lane >> 4) & 1) * 8;
    const int akb  = (lane >> 4) * 16;
    const int bkb  = ((lane >> 3) & 1) * 16;

    #pragma unroll
    for (int ks = 0; ks < 4; ks++) {
      uint32_t ah[4][4], bh[2][4];
      #pragma unroll
      for (int mt = 0; mt < 4; mt++) {
        const uint32_t off = SWZ((uint32_t)((arow + mt * 16) * 128 + ks * 32 + akb));
        ldm4(ah[mt], tb + off);
      }
      #pragma unroll
      for (int p = 0; p < 2; p++) {
        const uint32_t off = SWZ((uint32_t)((brow + p * 16) * 128 + ks * 32 + bkb));
        ldm4(bh[p], tb + 16384 + off);
      }
      #pragma unroll
      for (int mt = 0; mt < 4; mt++)
        #pragma unroll
        for (int p = 0; p < 2; p++) {
          mma16816(acc[mt][2 * p],     ah[mt], &bh[p][0]);
          mma16816(acc[mt][2 * p + 1], ah[mt], &bh[p][2]);
        }
    }
    __syncthreads();
  }

  const int r0 = bm + wrow * 64 + (lane >> 2);
  const int c0 = bn + wcol * 32 + (lane & 3) * 2;
  #pragma unroll
  for (int mt = 0; mt < 4; mt++)
    #pragma unroll
    for (int nt = 0; nt < 4; nt++) {
      const int col = c0 + nt * 8;
      if (col < N) {
        const int row = r0 + mt * 16;
        *(float2*)&C[(size_t)row * ldc + col] =
            make_float2(acc[mt][nt][0], acc[mt][nt][1]);
        *(float2*)&C[(size_t)(row + 8) * ldc + col] =
            make_float2(acc[mt][nt][2], acc[mt][nt][3]);
      }
    }
}

// ---------------- fp32 -> fp16 cast ------------------------------------------
__global__ void tofp16_kernel(const float* __restrict__ src,
                              __half* __restrict__ dst, int n) {
  int i = blockIdx.x * 256 + threadIdx.x;
  if (i < n) dst[i] = __float2half(src[i]);
}

// ---------------- W transpose -> fp16: out[n][k] = W[k][n] -------------------
__global__ void wtrans_kernel(const float* __restrict__ W,
                              __half* __restrict__ th, int K, int N) {
  __shared__ float t[32][33];
  const int n0 = blockIdx.x * 32, k0 = blockIdx.y * 32;
  const int tx = threadIdx.x, ty = threadIdx.y;
  #pragma unroll
  for (int r = 0; r < 4; r++) {
    int k = k0 + ty + r * 8, n = n0 + tx;
    t[ty + r * 8][tx] = (n < N) ? W[(size_t)k * N + n] : 0.f;
  }
  __syncthreads();
  #pragma unroll
  for (int r = 0; r < 4; r++) {
    int n = n0 + ty + r * 8, k = k0 + tx;
    th[(size_t)n * K + k] = __float2half(t[tx][ty + r * 8]);
  }
}

// ---------------- depthwise causal conv + bias + SiLU (8 steps/thread) ------
__global__ __launch_bounds__(128) void conv_kernel(const float* __restrict__ cw,
                                                   const float* __restrict__ cb) {
  const int ch  = blockIdx.x * 128 + threadIdx.x;
  const int grp = blockIdx.y;
  const size_t pos0 = (size_t)grp * 8;
  const int l0 = (int)(pos0 & (SEQLEN - 1));
  const float* src = g_zx + pos0 * DPROJ + DINNER + ch;
  const float w0 = cw[ch * 4 + 0], w1 = cw[ch * 4 + 1];
  const float w2 = cw[ch * 4 + 2], w3 = cw[ch * 4 + 3];
  const float bias = cb[ch];
  float v[11];
  #pragma unroll
  for (int j = 0; j < 3; j++)
    v[j] = (l0 >= 3 - j) ? src[(ptrdiff_t)(j - 3) * DPROJ] : 0.f;
  #pragma unroll
  for (int j = 0; j < 8; j++)
    v[3 + j] = src[(ptrdiff_t)j * DPROJ];
  float* dst = g_xbc + pos0 * CONVDIM + ch;
  #pragma unroll
  for (int j = 0; j < 8; j++) {
    float a = bias + w0 * v[j] + w1 * v[j + 1] + w2 * v[j + 2] + w3 * v[j + 3];
    dst[(size_t)j * CONVDIM] = a / (1.f + __expf(-a));
  }
}

// ---------------- dt softplus + log-decay -----------------------------------
__global__ void dt_kernel(const float* __restrict__ dtb, const float* __restrict__ alog) {
  int idx = blockIdx.x * 256 + threadIdx.x;
  int h = idx & (NH - 1);
  int pos = idx >> 4;
  float v = g_zx[(size_t)pos * DPROJ + DINNER + CONVDIM + h] + dtb[h];
  float sp = (v > 20.f) ? v : log1pf(expf(v));
  g_dt[idx] = sp;
  g_la[idx] = -expf(alog[h]) * sp;
}

// ---------------- per-chunk inclusive cumsum (one warp per chunk) -----------
__global__ void cumlog_kernel() {
  const int gw = (blockIdx.x * 256 + threadIdx.x) >> 5;
  const int lane = threadIdx.x & 31;
  const int c = gw & (NC - 1);
  const int bh = gw >> 6;
  const int b = bh >> 4, h = bh & (NH - 1);
  const int t0 = c * CS;
  float x0 = g_la[((b * SEQLEN + t0 + lane) << 4) + h];
  float x1 = g_la[((b * SEQLEN + t0 + 32 + lane) << 4) + h];
  #pragma unroll
  for (int o = 1; o < 32; o <<= 1) {
    float v = __shfl_up_sync(0xFFFFFFFFu, x0, o);
    if (lane >= o) x0 += v;
  }
  float tot0 = __shfl_sync(0xFFFFFFFFu, x0, 31);
  #pragma unroll
  for (int o = 1; o < 32; o <<= 1) {
    float v = __shfl_up_sync(0xFFFFFFFFu, x1, o);
    if (lane >= o) x1 += v;
  }
  x1 += tot0;
  g_cl[bh * SEQLEN + t0 + lane] = x0;
  g_cl[bh * SEQLEN + t0 + 32 + lane] = x1;
}

// ---------------- intra-chunk SSD kernel (HMMA) -------------------------------
// fp16 tiles, ld = 72 halves (144B rows, 16B aligned, conflict-free ldmatrix).
#define CLDH 72
#define CLDB 144
#define CH_SMEM (27648 * 2 + 192 * 4)   // 6 half tiles + 3 float[64]

__global__ __launch_bounds__(256) void chunk_kernel(const float* __restrict__ Dv) {
  extern __shared__ __half sh[];
  __half* sC  = sh;            // [64][72] C[t][n]
  __half* sB  = sh + 4608;     // [64][72] B[s][n]
  __half* sBt = sh + 9216;     // [64][72] Bt[n][s]
  __half* sXt = sh + 13824;    // [64][72] Xt[p][s]
  __half* sM  = sh + 18432;    // [64][72] M[t][s]
  __half* sXW = sh + 23040;    // [64][72] XWt[p][s]
  float* scl = (float*)(sh + 27648);
  float* sdt = scl + 64;

  const int bid = blockIdx.x;
  const int c = bid & (NC - 1);
  const int bh = bid >> 6;
  const int h = bh & (NH - 1);
  const int b = bh >> 4;
  const int tid = threadIdx.x;
  const int t0 = c * CS;
  const int wid = tid >> 5, lane = tid & 31;

  // ---- load & convert (each thread: one row, 16 cols) ----
  {
    const int row = tid >> 2, cs = (tid & 3) * 16;
    const float* base = g_xbc + (size_t)(b * SEQLEN + t0 + row) * CONVDIM;
    #pragma unroll
    for (int q = 0; q < 4; q++) {
      const int col = cs + q * 4;
      float4 vc = *(const float4*)(base + DINNER + DSTATE + col);
      float4 vb = *(const float4*)(base + DINNER + col);
      float4 vx = *(const float4*)(base + h * HD + col);
      const int o = row * CLDH + col;
      sC[o + 0] = __float2half(vc.x); sC[o + 1] = __float2half(vc.y);
      sC[o + 2] = __float2half(vc.z); sC[o + 3] = __float2half(vc.w);
      __half b0 = __float2half(vb.x), b1 = __float2half(vb.y);
      __half b2 = __float2half(vb.z), b3 = __float2half(vb.w);
      sB[o + 0] = b0; sB[o + 1] = b1; sB[o + 2] = b2; sB[o + 3] = b3;
      sBt[(col + 0) * CLDH + row] = b0; sBt[(col + 1) * CLDH + row] = b1;
      sBt[(col + 2) * CLDH + row] = b2; sBt[(col + 3) * CLDH + row] = b3;
      sXt[(col + 0) * CLDH + row] = __float2half(vx.x);
      sXt[(col + 1) * CLDH + row] = __float2half(vx.y);
      sXt[(col + 2) * CLDH + row] = __float2half(vx.z);
      sXt[(col + 3) * CLDH + row] = __float2half(vx.w);
    }
    if (tid < 64) {
      scl[tid] = g_cl[bh * SEQLEN + t0 + tid];
      sdt[tid] = g_dt[(b * SEQLEN + t0 + tid) * NH + h];
    }
  }
  __syncthreads();

  const uint32_t uC = smem_u32(sC), uB = smem_u32(sB), uBt = smem_u32(sBt);
  const uint32_t uXt = smem_u32(sXt), uM = smem_u32(sM), uXW = smem_u32(sXW);
  const int mt0 = (wid & 3) * 16;            // warp m-rows
  const int nt0 = (wid >> 2) * 32;           // warp n-cols
  const int aoff = (lane & 15) * CLDB + (lane >> 4) * 16;
  const int boff = ((lane & 7) + ((lane >> 4) & 1) * 8) * CLDB + ((lane >> 3) & 1) * 16;
  const int rb = mt0 + (lane >> 2);
  const int cb = nt0 + (lane & 3) * 2;

  float acc[4][4];

  // ---- GEMM1: M0 = C @ B^T ----
  #pragma unroll
  for (int nt = 0; nt < 4; nt++)
    #pragma unroll
    for (int v = 0; v < 4; v++) acc[nt][v] = 0.f;
  #pragma unroll
  for (int ks = 0; ks < 4; ks++) {
    uint32_t af[4];
    ldm4(af, uC + (uint32_t)(mt0 * CLDB + aoff + ks * 32));
    #pragma unroll
    for (int p = 0; p < 2; p++) {
      uint32_t bf[4];
      ldm4(bf, uB + (uint32_t)((nt0 + p * 16) * CLDB + boff + ks * 32));
      mma16816(acc[2 * p],     af, &bf[0]);
      mma16816(acc[2 * p + 1], af, &bf[2]);
    }
  }
  // mask/exp -> fp16 M
  #pragma unroll
  for (int nt = 0; nt < 4; nt++)
    #pragma unroll
    for (int cc = 0; cc < 4; cc++) {
      const int t = rb + ((cc >> 1) << 3);
      const int s = cb + nt * 8 + (cc & 1);
      float v = acc[nt][cc];
      v = (s <= t) ? v * __expf(scl[t] - scl[s]) * sdt[s] : 0.f;
      sM[t * CLDH + s] = __float2half(v);
    }
  // XWt[p][s] = Xt[p][s] * w[s],  w[s] = exp(Ltot - cl[s]) * dt[s]
  {
    const float Ltot = scl[63];
    const int row = tid >> 2, cs = (tid & 3) * 16;
    #pragma unroll
    for (int j = 0; j < 16; j++) {
      const int s = cs + j;
      const float w = __expf(Ltot - scl[s]) * sdt[s];
      const int o = row * CLDH + s;
      sXW[o] = __float2half(__half2float(sXt[o]) * w);
    }
  }
  __syncthreads();

  // ---- GEMM2: Y = M @ X ----
  #pragma unroll
  for (int nt = 0; nt < 4; nt++)
    #pragma unroll
    for (int v = 0; v < 4; v++) acc[nt][v] = 0.f;
  #pragma unroll
  for (int ks = 0; ks < 4; ks++) {
    uint32_t af[4];
    ldm4(af, uM + (uint32_t)(mt0 * CLDB + aoff + ks * 32));
    #pragma unroll
    for (int p = 0; p < 2; p++) {
      uint32_t bf[4];
      ldm4(bf, uXt + (uint32_t)((nt0 + p * 16) * CLDB + boff + ks * 32));
      mma16816(acc[2 * p],     af, &bf[0]);
      mma16816(acc[2 * p + 1], af, &bf[2]);
    }
  }
  {
    const float Dh = Dv[h];
    #pragma unroll
    for (int nt = 0; nt < 4; nt++) {
      const int p = cb + nt * 8;
      const int t1 = rb, t2 = rb + 8;
      float2 o01 = make_float2(
          acc[nt][0] + Dh * __half2float(sXt[p * CLDH + t1]),
          acc[nt][1] + Dh * __half2float(sXt[(p + 1) * CLDH + t1]));
      float2 o23 = make_float2(
          acc[nt][2] + Dh * __half2float(sXt[p * CLDH + t2]),
          acc[nt][3] + Dh * __half2float(sXt[(p + 1) * CLDH + t2]));
      *(float2*)&g_y[(size_t)(b * SEQLEN + t0 + t1) * DINNER + h * HD + p] = o01;
      *(float2*)&g_y[(size_t)(b * SEQLEN + t0 + t2) * DINNER + h * HD + p] = o23;
    }
  }

  // ---- GEMM3: S = XW^T @ B ----
  #pragma unroll
  for (int nt = 0; nt < 4; nt++)
    #pragma unroll
    for (int v = 0; v < 4; v++) acc[nt][v] = 0.f;
  #pragma unroll
  for (int ks = 0; ks < 4; ks++) {
    uint32_t af[4];
    ldm4(af, uXW + (uint32_t)(mt0 * CLDB + aoff + ks * 32));
    #pragma unroll
    for (int p = 0; p < 2; p++) {
      uint32_t bf[4];
      ldm4(bf, uBt + (uint32_t)((nt0 + p * 16) * CLDB + boff + ks * 32));
      mma16816(acc[2 * p],     af, &bf[0]);
      mma16816(acc[2 * p + 1], af, &bf[2]);
    }
  }
  #pragma unroll
  for (int nt = 0; nt < 4; nt++) {
    const int n = cb + nt * 8;
    *(float2*)&g_S[(size_t)bid * 4096 + rb * 64 + n] =
        make_float2(acc[nt][0], acc[nt][1]);
    *(float2*)&g_S[(size_t)bid * 4096 + (rb + 8) * 64 + n] =
        make_float2(acc[nt][2], acc[nt][3]);
  }
}

// ---------------- inter-chunk state scan (32 x 8 blocks) --------------------
__global__ __launch_bounds__(128) void scan_kernel() {
  const int bh = blockIdx.x;
  const int slice = blockIdx.y;
  const int tid = threadIdx.x;
  const int off = slice * 512 + tid * 4;
  float run[4] = {0.f, 0.f, 0.f, 0.f};
  for (int c = 0; c < NC; c++) {
    float a = __expf(g_cl[bh * SEQLEN + c * CS + CS - 1]);
    float* p = g_S + (size_t)(bh * NC + c) * 4096 + off;
    float4 v = *(float4*)p;
    *(float4*)p = make_float4(run[0], run[1], run[2], run[3]);
    run[0] = a * run[0] + v.x;
    run[1] = a * run[1] + v.y;
    run[2] = a * run[2] + v.z;
    run[3] = a * run[3] + v.w;
  }
}

// ---------------- inter-chunk contribution (fp32) ---------------------------
__global__ __launch_bounds__(256) void inter_kernel() {
  __shared__ float sS[4160];
  __shared__ float sC[4160];
  __shared__ float scl[64];
  const int bid = blockIdx.x;
  const int c = bid & (NC - 1);
  const int bh = bid >> 6;
  const int h = bh & (NH - 1);
  const int b = bh >> 4;
  const int tid = threadIdx.x;
  const int t0 = c * CS;

  for (int i = tid; i < 1024; i += 256) {
    int row = i >> 4, col = (i & 15) << 2;
    float4 v = *(const float4*)(g_S + (size_t)bid * 4096 + row * 64 + col);
    int o = row * 65 + col;
    sS[o] = v.x; sS[o + 1] = v.y; sS[o + 2] = v.z; sS[o + 3] = v.w;
    float4 vc = *(const float4*)(g_xbc + (size_t)(b * SEQLEN + t0 + row) * CONVDIM
                                 + DINNER + DSTATE + col);
    sC[o] = vc.x; sC[o + 1] = vc.y; sC[o + 2] = vc.z; sC[o + 3] = vc.w;
  }
  if (tid < 64) scl[tid] = g_cl[bh * SEQLEN + t0 + tid];
  __syncthreads();

  const int tr = (tid >> 4) << 2;
  const int pc = (tid & 15) << 2;
  float acc[4][4];
  #pragma unroll
  for (int i = 0; i < 4; i++)
    #pragma unroll
    for (int j = 0; j < 4; j++) acc[i][j] = 0.f;
  for (int n = 0; n < 64; ++n) {
    float cf[4], sf[4];
    #pragma unroll
    for (int i = 0; i < 4; i++) cf[i] = sC[(tr + i) * 65 + n];
    #pragma unroll
    for (int j = 0; j < 4; j++) sf[j] = sS[(pc + j) * 65 + n];
    #pragma unroll
    for (int i = 0; i < 4; i++)
      #pragma unroll
      for (int j = 0; j < 4; j++) acc[i][j] += cf[i] * sf[j];
  }
  #pragma unroll
  for (int i = 0; i < 4; i++) {
    float e = __expf(scl[tr + i]);
    size_t o = (size_t)(b * SEQLEN + t0 + tr + i) * DINNER + h * HD + pc;
    float4 cur = *(float4*)(g_y + o);
    cur.x += e * acc[i][0]; cur.y += e * acc[i][1];
    cur.z += e * acc[i][2]; cur.w += e * acc[i][3];
    *(float4*)(g_y + o) = cur;
  }
}

// ---------------- gate + RMSNorm, emits fp16 ---------------------------------
__global__ __launch_bounds__(256) void norm_kernel(const float* __restrict__ nw) {
  const int pos = blockIdx.x, tid = threadIdx.x;
  float4 yv = *(const float4*)(g_y  + (size_t)pos * DINNER + tid * 4);
  float4 zv = *(const float4*)(g_zx + (size_t)pos * DPROJ  + tid * 4);
  float4 g;
  g.x = yv.x * (zv.x / (1.f + __expf(-zv.x)));
  g.y = yv.y * (zv.y / (1.f + __expf(-zv.y)));
  g.z = yv.z * (zv.z / (1.f + __expf(-zv.z)));
  g.w = yv.w * (zv.w / (1.f + __expf(-zv.w)));
  float ssq = g.x * g.x + g.y * g.y + g.z * g.z + g.w * g.w;
  #pragma unroll
  for (int o = 16; o; o >>= 1) ssq += __shfl_xor_sync(0xFFFFFFFFu, ssq, o);
  __shared__ float red[8];
  if ((tid & 31) == 0) red[tid >> 5] = ssq;
  __syncthreads();
  float tot = red[0] + red[1] + red[2] + red[3] + red[4] + red[5] + red[6] + red[7];
  float scale = rsqrtf(tot * (1.f / DINNER) + EPSV);
  float4 w = *(const float4*)(nw + tid * 4);
  __half2* dst = (__half2*)(g_yh + (size_t)pos * DINNER + tid * 4);
  dst[0] = __floats2half2_rn(g.x * scale * w.x, g.y * scale * w.y);
  dst[1] = __floats2half2_rn(g.z * scale * w.z, g.w * scale * w.w);
}

// ---------------- launch ------------------------------------------------------
extern "C" void kernel_launch(void* const* d_in, const int* in_sizes, int n_in,
                              void* d_out, int out_size) {
  const float* x       = (const float*)d_in[0];
  const float* W_in    = (const float*)d_in[1];
  const float* conv_w  = (const float*)d_in[2];
  const float* conv_b  = (const float*)d_in[3];
  const float* dt_bias = (const float*)d_in[4];
  const float* A_log   = (const float*)d_in[5];
  const float* Dv      = (const float*)d_in[6];
  const float* nw      = (const float*)d_in[7];
  const float* W_out   = (const float*)d_in[8];
  float* out = (float*)d_out;

  void* p;
  cudaGetSymbolAddress(&p, g_zx);  float* zx = (float*)p;
  cudaGetSymbolAddress(&p, g_xh);  __half* xh  = (__half*)p;
  cudaGetSymbolAddress(&p, g_w1h); __half* w1h = (__half*)p;
  cudaGetSymbolAddress(&p, g_yh);  __half* yh  = (__half*)p;
  cudaGetSymbolAddress(&p, g_w2h); __half* w2h = (__half*)p;

  cudaFuncSetAttribute(chunk_kernel, cudaFuncAttributeMaxDynamicSharedMemorySize, CH_SMEM);
  cudaFuncSetAttribute(gemm_tc, cudaFuncAttributeMaxDynamicSharedMemorySize, SM_TOTAL);

  dim3 blk(256);
  tofp16_kernel<<<(NPOS * DMODEL) / 256, blk>>>(x, xh, NPOS * DMODEL);
  wtrans_kernel<<<dim3(NPAD1 / 32, DMODEL / 32), dim3(32, 8)>>>(W_in, w1h, DMODEL, DPROJ);
  wtrans_kernel<<<dim3(DMODEL / 32, DINNER / 32), dim3(32, 8)>>>(W_out, w2h, DINNER, DMODEL);
  // 1) in-projection (fp16 HMMA)
  gemm_tc<<<dim3(NPAD1 / 128, NPOS / 128), blk, SM_TOTAL>>>(xh, w1h, zx,
                                                            DMODEL, DPROJ, DPROJ);
  // 2) conv + silu
  conv_kernel<<<dim3(CONVDIM / 128, NPOS / 8), dim3(128)>>>(conv_w, conv_b);
  // 3) dt
  dt_kernel<<<(NPOS * NH) / 256, blk>>>(dt_bias, A_log);
  // 4) cumlog
  cumlog_kernel<<<(BATCH * NH * NC * 32) / 256, blk>>>();
  // 5) intra-chunk SSD (HMMA)
  chunk_kernel<<<BATCH * NH * NC, blk, CH_SMEM>>>(Dv);
  // 6) inter-chunk state scan
  scan_kernel<<<dim3(BATCH * NH, 8), dim3(128)>>>();
  // 7) inter-chunk correction
  inter_kernel<<<BATCH * NH * NC, blk>>>();
  // 8) gate + RMSNorm
  norm_kernel<<<NPOS, blk>>>(nw);
  // 9) out-projection (fp16 HMMA)
  gemm_tc<<<dim3(DMODEL / 128, NPOS / 128), blk, SM_TOTAL>>>(yh, w2h, out,
                                                             DINNER, DMODEL, DMODEL);
}

// round 6
// speedup vs baseline: 4.8124x; 1.2057x over previous
#include <cuda_runtime.h>
#include <cuda_fp16.h>
#include <cstdint>
#include <cstddef>

#define BATCH   2
#define SEQLEN  4096
#define DMODEL  512
#define DINNER  1024
#define NH      16
#define HD      64
#define DSTATE  64
#define CONVDIM 1152
#define DPROJ   2192
#define NPOS    (BATCH * SEQLEN)   // 8192
#define NC      64
#define CS      64
#define EPSV    1e-5f
#define NPAD1   2304

// ---------------- scratch (static device globals) ---------------------------
__device__ float  g_zx [(size_t)NPOS * DPROJ];
__device__ __half g_xbc[(size_t)NPOS * CONVDIM];   // fp16: conv output
__device__ float  g_dt [NPOS * NH];
__device__ float  g_cl [BATCH * NH * SEQLEN];
__device__ float  g_S  [(size_t)BATCH * NH * NC * HD * DSTATE];
__device__ float  g_y  [(size_t)NPOS * DINNER];

__device__ __half g_xh [(size_t)NPOS * DMODEL];
__device__ __half g_w1h[(size_t)NPAD1 * DMODEL];
__device__ __half g_yh [(size_t)NPOS * DINNER];
__device__ __half g_w2h[(size_t)DMODEL * DINNER];

// ---------------- PTX helpers ------------------------------------------------
__device__ __forceinline__ uint32_t smem_u32(const void* p) {
  uint32_t a;
  asm("{ .reg .u64 t; cvta.to.shared.u64 t, %1; cvt.u32.u64 %0, t; }" : "=r"(a) : "l"(p));
  return a;
}
__device__ __forceinline__ void ldm4(uint32_t* r, uint32_t addr) {
  asm volatile("ldmatrix.sync.aligned.m8n8.x4.shared.b16 {%0,%1,%2,%3}, [%4];"
               : "=r"(r[0]), "=r"(r[1]), "=r"(r[2]), "=r"(r[3]) : "r"(addr));
}
__device__ __forceinline__ void mma16816(float* c, const uint32_t* a, const uint32_t* b) {
  asm volatile(
      "mma.sync.aligned.m16n8k16.row.col.f32.f16.f16.f32 "
      "{%0,%1,%2,%3}, {%4,%5,%6,%7}, {%8,%9}, {%0,%1,%2,%3};"
      : "+f"(c[0]), "+f"(c[1]), "+f"(c[2]), "+f"(c[3])
      : "r"(a[0]), "r"(a[1]), "r"(a[2]), "r"(a[3]), "r"(b[0]), "r"(b[1]));
}
#define CPASYNC(dst, src) \
  asm volatile("cp.async.cg.shared.global [%0], [%1], 16;" :: "r"(dst), "l"(src))
#define CPCOMMIT() asm volatile("cp.async.commit_group;" ::: "memory")
#define CPWAIT(n)  asm volatile("cp.async.wait_group %0;" :: "n"(n) : "memory")
#define SWZ(off)   ((off) ^ (((off) >> 3) & 0x70))

// ---------------- HMMA GEMM (fp16): C = A @ B^T ------------------------------
#define SM_BUF   32768
#define SM_TOTAL (2 * SM_BUF)

__global__ __launch_bounds__(256, 2) void gemm_tc(
    const __half* __restrict__ A, const __half* __restrict__ B,
    float* __restrict__ C, int K, int N, int ldc) {
  extern __shared__ char smem[];
  const uint32_t sb = smem_u32(smem);
  const int tid = threadIdx.x, wid = tid >> 5, lane = tid & 31;
  const int bm = blockIdx.y * 128, bn = blockIdx.x * 128;
  const int wrow = wid & 1, wcol = wid >> 1;

  float acc[4][4][4];
  #pragma unroll
  for (int i = 0; i < 4; i++)
    #pragma unroll
    for (int j = 0; j < 4; j++)
      #pragma unroll
      for (int v = 0; v < 4; v++) acc[i][j][v] = 0.f;

  const int nK = K >> 6;
  {
    #pragma unroll
    for (int it = 0; it < 8; it++) {
      const int u = it * 256 + tid;
      const int tile = u >> 10, idx = u & 1023;
      const int row = idx >> 3, c16 = idx & 7;
      const uint32_t dst = sb + tile * 16384 + SWZ((uint32_t)(row * 128 + c16 * 16));
      const __half* src = (tile == 0) ? A + (size_t)(bm + row) * K + c16 * 8
                                      : B + (size_t)(bn + row) * K + c16 * 8;
      CPASYNC(dst, src);
    }
    CPCOMMIT();
  }

  for (int i = 0; i < nK; i++) {
    if (i + 1 < nK) {
      const int k0 = (i + 1) << 6;
      const uint32_t bbuf = sb + ((i + 1) & 1) * SM_BUF;
      #pragma unroll
      for (int it = 0; it < 8; it++) {
        const int u = it * 256 + tid;
        const int tile = u >> 10, idx = u & 1023;
        const int row = idx >> 3, c16 = idx & 7;
        const uint32_t dst = bbuf + tile * 16384 + SWZ((uint32_t)(row * 128 + c16 * 16));
        const __half* src = (tile == 0) ? A + (size_t)(bm + row) * K + k0 + c16 * 8
                                        : B + (size_t)(bn + row) * K + k0 + c16 * 8;
        CPASYNC(dst, src);
      }
      CPCOMMIT();
      CPWAIT(1);
    } else {
      CPWAIT(0);
    }
    __syncthreads();

    const uint32_t tb = sb + (i & 1) * SM_BUF;
    const int arow = wrow * 64 + (lane & 15);
    const int brow = wcol * 32 + (lane & 7) + ((lane >> 4) & 1) * 8;
    const int akb  = (lane >> 4) * 16;
    const int bkb  = ((lane >> 3) & 1) * 16;

    #pragma unroll
    for (int ks = 0; ks < 4; ks++) {
      uint32_t ah[4][4], bh[2][4];
      #pragma unroll
      for (int mt = 0; mt < 4; mt++) {
        const uint32_t off = SWZ((uint32_t)((arow + mt * 16) * 128 + ks * 32 + akb));
        ldm4(ah[mt], tb + off);
      }
      #pragma unroll
      for (int p = 0; p < 2; p++) {
        const uint32_t off = SWZ((uint32_t)((brow + p * 16) * 128 + ks * 32 + bkb));
        ldm4(bh[p], tb + 16384 + off);
      }
      #pragma unroll
      for (int mt = 0; mt < 4; mt++)
        #pragma unroll
        for (int p = 0; p < 2; p++) {
          mma16816(acc[mt][2 * p],     ah[mt], &bh[p][0]);
          mma16816(acc[mt][2 * p + 1], ah[mt], &bh[p][2]);
        }
    }
    __syncthreads();
  }

  const int r0 = bm + wrow * 64 + (lane >> 2);
  const int c0 = bn + wcol * 32 + (lane & 3) * 2;
  #pragma unroll
  for (int mt = 0; mt < 4; mt++)
    #pragma unroll
    for (int nt = 0; nt < 4; nt++) {
      const int col = c0 + nt * 8;
      if (col < N) {
        const int row = r0 + mt * 16;
        *(float2*)&C[(size_t)row * ldc + col] =
            make_float2(acc[mt][nt][0], acc[mt][nt][1]);
        *(float2*)&C[(size_t)(row + 8) * ldc + col] =
            make_float2(acc[mt][nt][2], acc[mt][nt][3]);
      }
    }
}

// ---------------- fp32 -> fp16 cast ------------------------------------------
__global__ void tofp16_kernel(const float* __restrict__ src,
                              __half* __restrict__ dst, int n) {
  int i = blockIdx.x * 256 + threadIdx.x;
  if (i < n) dst[i] = __float2half(src[i]);
}

// ---------------- W transpose -> fp16 ----------------------------------------
__global__ void wtrans_kernel(const float* __restrict__ W,
                              __half* __restrict__ th, int K, int N) {
  __shared__ float t[32][33];
  const int n0 = blockIdx.x * 32, k0 = blockIdx.y * 32;
  const int tx = threadIdx.x, ty = threadIdx.y;
  #pragma unroll
  for (int r = 0; r < 4; r++) {
    int k = k0 + ty + r * 8, n = n0 + tx;
    t[ty + r * 8][tx] = (n < N) ? W[(size_t)k * N + n] : 0.f;
  }
  __syncthreads();
  #pragma unroll
  for (int r = 0; r < 4; r++) {
    int n = n0 + ty + r * 8, k = k0 + tx;
    th[(size_t)n * K + k] = __float2half(t[tx][ty + r * 8]);
  }
}

// ---------------- depthwise conv + bias + SiLU -> fp16 -----------------------
__global__ __launch_bounds__(128) void conv_kernel(const float* __restrict__ cw,
                                                   const float* __restrict__ cb) {
  const int ch  = blockIdx.x * 128 + threadIdx.x;
  const int grp = blockIdx.y;
  const size_t pos0 = (size_t)grp * 8;
  const int l0 = (int)(pos0 & (SEQLEN - 1));
  const float* src = g_zx + pos0 * DPROJ + DINNER + ch;
  const float w0 = cw[ch * 4 + 0], w1 = cw[ch * 4 + 1];
  const float w2 = cw[ch * 4 + 2], w3 = cw[ch * 4 + 3];
  const float bias = cb[ch];
  float v[11];
  #pragma unroll
  for (int j = 0; j < 3; j++)
    v[j] = (l0 >= 3 - j) ? src[(ptrdiff_t)(j - 3) * DPROJ] : 0.f;
  #pragma unroll
  for (int j = 0; j < 8; j++)
    v[3 + j] = src[(ptrdiff_t)j * DPROJ];
  __half* dst = g_xbc + pos0 * CONVDIM + ch;
  #pragma unroll
  for (int j = 0; j < 8; j++) {
    float a = bias + w0 * v[j] + w1 * v[j + 1] + w2 * v[j + 2] + w3 * v[j + 3];
    dst[(size_t)j * CONVDIM] = __float2half(a / (1.f + __expf(-a)));
  }
}

// ---------------- fused dt softplus + per-chunk cumsum (warp/chunk) ---------
__global__ void dtscan_kernel(const float* __restrict__ dtb,
                              const float* __restrict__ alog) {
  const int gw = (blockIdx.x * 256 + threadIdx.x) >> 5;   // 0..2047
  const int lane = threadIdx.x & 31;
  const int c = gw & (NC - 1);
  const int bh = gw >> 6;
  const int b = bh >> 4, h = bh & (NH - 1);
  const int t0 = c * CS;
  const int pos0 = b * SEQLEN + t0 + lane;
  const float bsh = dtb[h];
  const float A = -expf(alog[h]);
  float v0 = g_zx[(size_t)pos0 * DPROJ + DINNER + CONVDIM + h] + bsh;
  float v1 = g_zx[(size_t)(pos0 + 32) * DPROJ + DINNER + CONVDIM + h] + bsh;
  float sp0 = (v0 > 20.f) ? v0 : log1pf(expf(v0));
  float sp1 = (v1 > 20.f) ? v1 : log1pf(expf(v1));
  g_dt[pos0 * NH + h] = sp0;
  g_dt[(pos0 + 32) * NH + h] = sp1;
  float x0 = A * sp0, x1 = A * sp1;
  #pragma unroll
  for (int o = 1; o < 32; o <<= 1) {
    float t = __shfl_up_sync(0xFFFFFFFFu, x0, o);
    if (lane >= o) x0 += t;
  }
  float tot0 = __shfl_sync(0xFFFFFFFFu, x0, 31);
  #pragma unroll
  for (int o = 1; o < 32; o <<= 1) {
    float t = __shfl_up_sync(0xFFFFFFFFu, x1, o);
    if (lane >= o) x1 += t;
  }
  x1 += tot0;
  g_cl[bh * SEQLEN + t0 + lane] = x0;
  g_cl[bh * SEQLEN + t0 + 32 + lane] = x1;
}

// ---------------- intra-chunk SSD kernel (HMMA, fp16 inputs) -----------------
#define CLDH 72
#define CLDB 144
#define CH_SMEM (27648 * 2 + 192 * 4)

__global__ __launch_bounds__(256) void chunk_kernel(const float* __restrict__ Dv) {
  extern __shared__ __align__(16) __half sh[];
  __half* sC  = sh;            // [64][72] C[t][n]
  __half* sB  = sh + 4608;     // [64][72] B[s][n]
  __half* sBt = sh + 9216;     // [64][72] Bt[n][s]
  __half* sXt = sh + 13824;    // [64][72] Xt[p][s]
  __half* sM  = sh + 18432;    // [64][72] M[t][s]
  __half* sXW = sh + 23040;    // [64][72] XWt[p][s]
  float* scl = (float*)(sh + 27648);
  float* sdt = scl + 64;

  const int bid = blockIdx.x;
  const int c = bid & (NC - 1);
  const int bh = bid >> 6;
  const int h = bh & (NH - 1);
  const int b = bh >> 4;
  const int tid = threadIdx.x;
  const int t0 = c * CS;
  const int wid = tid >> 5, lane = tid & 31;

  // ---- load fp16 tiles (each thread: one row, 16 cols) ----
  {
    const int row = tid >> 2, cs = (tid & 3) * 16;
    const __half* base = g_xbc + (size_t)(b * SEQLEN + t0 + row) * CONVDIM;
    #pragma unroll
    for (int q = 0; q < 2; q++) {
      const int col = cs + q * 8;
      uint4 vb = *(const uint4*)(base + DINNER + col);
      uint4 vc = *(const uint4*)(base + DINNER + DSTATE + col);
      uint4 vx = *(const uint4*)(base + h * HD + col);
      *(uint4*)(sB + row * CLDH + col) = vb;
      *(uint4*)(sC + row * CLDH + col) = vc;
      const __half* hb = (const __half*)&vb;
      const __half* hx = (const __half*)&vx;
      #pragma unroll
      for (int j = 0; j < 8; j++) {
        sBt[(col + j) * CLDH + row] = hb[j];
        sXt[(col + j) * CLDH + row] = hx[j];
      }
    }
    if (tid < 64) {
      scl[tid] = g_cl[bh * SEQLEN + t0 + tid];
      sdt[tid] = g_dt[(b * SEQLEN + t0 + tid) * NH + h];
    }
  }
  __syncthreads();

  const uint32_t uC = smem_u32(sC), uB = smem_u32(sB), uBt = smem_u32(sBt);
  const uint32_t uXt = smem_u32(sXt), uM = smem_u32(sM), uXW = smem_u32(sXW);
  const int mt0 = (wid & 3) * 16;
  const int nt0 = (wid >> 2) * 32;
  const int aoff = (lane & 15) * CLDB + (lane >> 4) * 16;
  const int boff = ((lane & 7) + ((lane >> 4) & 1) * 8) * CLDB + ((lane >> 3) & 1) * 16;
  const int rb = mt0 + (lane >> 2);
  const int cb = nt0 + (lane & 3) * 2;

  float acc[4][4];

  // ---- GEMM1: M0 = C @ B^T ----
  #pragma unroll
  for (int nt = 0; nt < 4; nt++)
    #pragma unroll
    for (int v = 0; v < 4; v++) acc[nt][v] = 0.f;
  #pragma unroll
  for (int ks = 0; ks < 4; ks++) {
    uint32_t af[4];
    ldm4(af, uC + (uint32_t)(mt0 * CLDB + aoff + ks * 32));
    #pragma unroll
    for (int p = 0; p < 2; p++) {
      uint32_t bf[4];
      ldm4(bf, uB + (uint32_t)((nt0 + p * 16) * CLDB + boff + ks * 32));
      mma16816(acc[2 * p],     af, &bf[0]);
      mma16816(acc[2 * p + 1], af, &bf[2]);
    }
  }
  #pragma unroll
  for (int nt = 0; nt < 4; nt++)
    #pragma unroll
    for (int cc = 0; cc < 4; cc++) {
      const int t = rb + ((cc >> 1) << 3);
      const int s = cb + nt * 8 + (cc & 1);
      float v = acc[nt][cc];
      v = (s <= t) ? v * __expf(scl[t] - scl[s]) * sdt[s] : 0.f;
      sM[t * CLDH + s] = __float2half(v);
    }
  {
    const float Ltot = scl[63];
    const int row = tid >> 2, cs = (tid & 3) * 16;
    #pragma unroll
    for (int j = 0; j < 16; j++) {
      const int s = cs + j;
      const float w = __expf(Ltot - scl[s]) * sdt[s];
      const int o = row * CLDH + s;
      sXW[o] = __float2half(__half2float(sXt[o]) * w);
    }
  }
  __syncthreads();

  // ---- GEMM2: Y = M @ X ----
  #pragma unroll
  for (int nt = 0; nt < 4; nt++)
    #pragma unroll
    for (int v = 0; v < 4; v++) acc[nt][v] = 0.f;
  #pragma unroll
  for (int ks = 0; ks < 4; ks++) {
    uint32_t af[4];
    ldm4(af, uM + (uint32_t)(mt0 * CLDB + aoff + ks * 32));
    #pragma unroll
    for (int p = 0; p < 2; p++) {
      uint32_t bf[4];
      ldm4(bf, uXt + (uint32_t)((nt0 + p * 16) * CLDB + boff + ks * 32));
      mma16816(acc[2 * p],     af, &bf[0]);
      mma16816(acc[2 * p + 1], af, &bf[2]);
    }
  }
  {
    const float Dh = Dv[h];
    #pragma unroll
    for (int nt = 0; nt < 4; nt++) {
      const int p = cb + nt * 8;
      const int t1 = rb, t2 = rb + 8;
      float2 o01 = make_float2(
          acc[nt][0] + Dh * __half2float(sXt[p * CLDH + t1]),
          acc[nt][1] + Dh * __half2float(sXt[(p + 1) * CLDH + t1]));
      float2 o23 = make_float2(
          acc[nt][2] + Dh * __half2float(sXt[p * CLDH + t2]),
          acc[nt][3] + Dh * __half2float(sXt[(p + 1) * CLDH + t2]));
      *(float2*)&g_y[(size_t)(b * SEQLEN + t0 + t1) * DINNER + h * HD + p] = o01;
      *(float2*)&g_y[(size_t)(b * SEQLEN + t0 + t2) * DINNER + h * HD + p] = o23;
    }
  }

  // ---- GEMM3: S = XW^T @ B ----
  #pragma unroll
  for (int nt = 0; nt < 4; nt++)
    #pragma unroll
    for (int v = 0; v < 4; v++) acc[nt][v] = 0.f;
  #pragma unroll
  for (int ks = 0; ks < 4; ks++) {
    uint32_t af[4];
    ldm4(af, uXW + (uint32_t)(mt0 * CLDB + aoff + ks * 32));
    #pragma unroll
    for (int p = 0; p < 2; p++) {
      uint32_t bf[4];
      ldm4(bf, uBt + (uint32_t)((nt0 + p * 16) * CLDB + boff + ks * 32));
      mma16816(acc[2 * p],     af, &bf[0]);
      mma16816(acc[2 * p + 1], af, &bf[2]);
    }
  }
  #pragma unroll
  for (int nt = 0; nt < 4; nt++) {
    const int n = cb + nt * 8;
    *(float2*)&g_S[(size_t)bid * 4096 + rb * 64 + n] =
        make_float2(acc[nt][0], acc[nt][1]);
    *(float2*)&g_S[(size_t)bid * 4096 + (rb + 8) * 64 + n] =
        make_float2(acc[nt][2], acc[nt][3]);
  }
}

// ---------------- inter-chunk state scan -------------------------------------
__global__ __launch_bounds__(128) void scan_kernel() {
  const int bh = blockIdx.x;
  const int slice = blockIdx.y;
  const int tid = threadIdx.x;
  const int off = slice * 512 + tid * 4;
  float run[4] = {0.f, 0.f, 0.f, 0.f};
  for (int c = 0; c < NC; c++) {
    float a = __expf(g_cl[bh * SEQLEN + c * CS + CS - 1]);
    float* p = g_S + (size_t)(bh * NC + c) * 4096 + off;
    float4 v = *(float4*)p;
    *(float4*)p = make_float4(run[0], run[1], run[2], run[3]);
    run[0] = a * run[0] + v.x;
    run[1] = a * run[1] + v.y;
    run[2] = a * run[2] + v.z;
    run[3] = a * run[3] + v.w;
  }
}

// ---------------- inter-chunk contribution (HMMA fp16) ----------------------
__global__ __launch_bounds__(256) void inter_kernel() {
  __shared__ __align__(16) __half sC[4608];   // [64][72] C[t][n]
  __shared__ __align__(16) __half sS[4608];   // [64][72] Sprev[p][n]
  __shared__ float scl[64];
  const int bid = blockIdx.x;
  const int c = bid & (NC - 1);
  const int bh = bid >> 6;
  const int h = bh & (NH - 1);
  const int b = bh >> 4;
  const int tid = threadIdx.x;
  const int t0 = c * CS;
  const int wid = tid >> 5, lane = tid & 31;

  {
    const int row = tid >> 2, cs = (tid & 3) * 16;
    const __half* cbase = g_xbc + (size_t)(b * SEQLEN + t0 + row) * CONVDIM
                          + DINNER + DSTATE;
    #pragma unroll
    for (int q = 0; q < 2; q++)
      *(uint4*)(sC + row * CLDH + cs + q * 8) = *(const uint4*)(cbase + cs + q * 8);
    #pragma unroll
    for (int q = 0; q < 4; q++) {
      float4 v = *(const float4*)(g_S + (size_t)bid * 4096 + row * 64 + cs + q * 4);
      __half2* d = (__half2*)(sS + row * CLDH + cs + q * 4);
      d[0] = __floats2half2_rn(v.x, v.y);
      d[1] = __floats2half2_rn(v.z, v.w);
    }
    if (tid < 64) scl[tid] = g_cl[bh * SEQLEN + t0 + tid];
  }
  __syncthreads();

  const uint32_t uC = smem_u32(sC), uS = smem_u32(sS);
  const int mt0 = (wid & 3) * 16;          // t rows
  const int nt0 = (wid >> 2) * 32;         // p cols
  const int aoff = (lane & 15) * CLDB + (lane >> 4) * 16;
  const int boff = ((lane & 7) + ((lane >> 4) & 1) * 8) * CLDB + ((lane >> 3) & 1) * 16;
  const int rb = mt0 + (lane >> 2);
  const int cb = nt0 + (lane & 3) * 2;

  float acc[4][4];
  #pragma unroll
  for (int nt = 0; nt < 4; nt++)
    #pragma unroll
    for (int v = 0; v < 4; v++) acc[nt][v] = 0.f;
  #pragma unroll
  for (int ks = 0; ks < 4; ks++) {
    uint32_t af[4];
    ldm4(af, uC + (uint32_t)(mt0 * CLDB + aoff + ks * 32));
    #pragma unroll
    for (int p = 0; p < 2; p++) {
      uint32_t bf[4];
      ldm4(bf, uS + (uint32_t)((nt0 + p * 16) * CLDB + boff + ks * 32));
      mma16816(acc[2 * p],     af, &bf[0]);
      mma16816(acc[2 * p + 1], af, &bf[2]);
    }
  }
  const float e1 = __expf(scl[rb]);
  const float e2 = __expf(scl[rb + 8]);
  #pragma unroll
  for (int nt = 0; nt < 4; nt++) {
    const int p = cb + nt * 8;
    size_t o1 = (size_t)(b * SEQLEN + t0 + rb) * DINNER + h * HD + p;
    size_t o2 = (size_t)(b * SEQLEN + t0 + rb + 8) * DINNER + h * HD + p;
    float2 c1 = *(float2*)&g_y[o1];
    float2 c2 = *(float2*)&g_y[o2];
    c1.x += e1 * acc[nt][0]; c1.y += e1 * acc[nt][1];
    c2.x += e2 * acc[nt][2]; c2.y += e2 * acc[nt][3];
    *(float2*)&g_y[o1] = c1;
    *(float2*)&g_y[o2] = c2;
  }
}

// ---------------- gate + RMSNorm, emits fp16 ---------------------------------
__global__ __launch_bounds__(256) void norm_kernel(const float* __restrict__ nw) {
  const int pos = blockIdx.x, tid = threadIdx.x;
  float4 yv = *(const float4*)(g_y  + (size_t)pos * DINNER + tid * 4);
  float4 zv = *(const float4*)(g_zx + (size_t)pos * DPROJ  + tid * 4);
  float4 g;
  g.x = yv.x * (zv.x / (1.f + __expf(-zv.x)));
  g.y = yv.y * (zv.y / (1.f + __expf(-zv.y)));
  g.z = yv.z * (zv.z / (1.f + __expf(-zv.z)));
  g.w = yv.w * (zv.w / (1.f + __expf(-zv.w)));
  float ssq = g.x * g.x + g.y * g.y + g.z * g.z + g.w * g.w;
  #pragma unroll
  for (int o = 16; o; o >>= 1) ssq += __shfl_xor_sync(0xFFFFFFFFu, ssq, o);
  __shared__ float red[8];
  if ((tid & 31) == 0) red[tid >> 5] = ssq;
  __syncthreads();
  float tot = red[0] + red[1] + red[2] + red[3] + red[4] + red[5] + red[6] + red[7];
  float scale = rsqrtf(tot * (1.f / DINNER) + EPSV);
  float4 w = *(const float4*)(nw + tid * 4);
  __half2* dst = (__half2*)(g_yh + (size_t)pos * DINNER + tid * 4);
  dst[0] = __floats2half2_rn(g.x * scale * w.x, g.y * scale * w.y);
  dst[1] = __floats2half2_rn(g.z * scale * w.z, g.w * scale * w.w);
}

// ---------------- launch ------------------------------------------------------
extern "C" void kernel_launch(void* const* d_in, const int* in_sizes, int n_in,
                              void* d_out, int out_size) {
  const float* x       = (const float*)d_in[0];
  const float* W_in    = (const float*)d_in[1];
  const float* conv_w  = (const float*)d_in[2];
  const float* conv_b  = (const float*)d_in[3];
  const float* dt_bias = (const float*)d_in[4];
  const float* A_log   = (const float*)d_in[5];
  const float* Dv      = (const float*)d_in[6];
  const float* nw      = (const float*)d_in[7];
  const float* W_out   = (const float*)d_in[8];
  float* out = (float*)d_out;

  void* p;
  cudaGetSymbolAddress(&p, g_zx);  float* zx = (float*)p;
  cudaGetSymbolAddress(&p, g_xh);  __half* xh  = (__half*)p;
  cudaGetSymbolAddress(&p, g_w1h); __half* w1h = (__half*)p;
  cudaGetSymbolAddress(&p, g_yh);  __half* yh  = (__half*)p;
  cudaGetSymbolAddress(&p, g_w2h); __half* w2h = (__half*)p;

  cudaFuncSetAttribute(chunk_kernel, cudaFuncAttributeMaxDynamicSharedMemorySize, CH_SMEM);
  cudaFuncSetAttribute(gemm_tc, cudaFuncAttributeMaxDynamicSharedMemorySize, SM_TOTAL);

  dim3 blk(256);
  tofp16_kernel<<<(NPOS * DMODEL) / 256, blk>>>(x, xh, NPOS * DMODEL);
  wtrans_kernel<<<dim3(NPAD1 / 32, DMODEL / 32), dim3(32, 8)>>>(W_in, w1h, DMODEL, DPROJ);
  wtrans_kernel<<<dim3(DMODEL / 32, DINNER / 32), dim3(32, 8)>>>(W_out, w2h, DINNER, DMODEL);
  // 1) in-projection (fp16 HMMA)
  gemm_tc<<<dim3(NPAD1 / 128, NPOS / 128), blk, SM_TOTAL>>>(xh, w1h, zx,
                                                            DMODEL, DPROJ, DPROJ);
  // 2) conv + silu -> fp16
  conv_kernel<<<dim3(CONVDIM / 128, NPOS / 8), dim3(128)>>>(conv_w, conv_b);
  // 3) fused dt + cumlog
  dtscan_kernel<<<(BATCH * NH * NC * 32) / 256, blk>>>(dt_bias, A_log);
  // 4) intra-chunk SSD (HMMA)
  chunk_kernel<<<BATCH * NH * NC, blk, CH_SMEM>>>(Dv);
  // 5) inter-chunk state scan
  scan_kernel<<<dim3(BATCH * NH, 8), dim3(128)>>>();
  // 6) inter-chunk correction (HMMA)
  inter_kernel<<<BATCH * NH * NC, blk>>>();
  // 7) gate + RMSNorm
  norm_kernel<<<NPOS, blk>>>(nw);
  // 8) out-projection (fp16 HMMA)
  gemm_tc<<<dim3(DMODEL / 128, NPOS / 128), blk, SM_TOTAL>>>(yh, w2h, out,
                                                             DINNER, DMODEL, DMODEL);
}